// round 13
// baseline (speedup 1.0000x reference)
#include <cuda_runtime.h>
#include <math.h>

#define NN 100000
#define EE 1000000
#define EP (EE + NN)
#define FF 128
#define CC 64
#define LL 4
#define NB1 98
#define RBLK 512
#define GBT 128
#define NT 128
#define SXS 68
#define GEMM_SMEM ((NT * SXS + 64 * 64) * 4)
#define GB ((NN + NT - 1) / NT)

__device__ float  g_h[NN * CC];
__device__ float  g_z[NN * CC];
__device__ float  g_hraw[NN * CC];
__device__ float  g_score[EP];
__device__ int    g_cnt[NN];
__device__ int    g_offs[NN + 1];
__device__ int    g_cur[NN];
__device__ int    g_elist[EP];
__device__ int    g_bsum[NB1 + 2];
__device__ float  g_part[RBLK * 128];
__device__ float  g_stat[128];
__device__ float  g_WTin[FF * CC];
__device__ float  g_WT[LL * CC * CC];
__device__ float  g_bp[CC];
__device__ int    g_rc = 0;

__device__ __forceinline__ float lrelu(float v, float s) { return v >= 0.f ? v : s * v; }

__device__ __forceinline__ void ffma2(unsigned long long &d, unsigned long long a,
                                      unsigned long long b) {
    asm("fma.rn.f32x2 %0, %1, %2, %0;" : "+l"(d) : "l"(a), "l"(b));
}
__device__ __forceinline__ unsigned long long pack2(float x) {
    unsigned long long r;
    unsigned int xi = __float_as_uint(x);
    asm("mov.b64 %0, {%1, %1};" : "=l"(r) : "r"(xi));
    return r;
}
__device__ __forceinline__ void unpack2(unsigned long long v, float &lo, float &hi) {
    unsigned int a, b;
    asm("mov.b64 {%0, %1}, %2;" : "=r"(a), "=r"(b) : "l"(v));
    lo = __uint_as_float(a); hi = __uint_as_float(b);
}

// ---------------- setup ------------------------------------------------------
__global__ void k_setup(const float* __restrict__ bn_w, const float* __restrict__ bn_b,
                        const float* __restrict__ bn_mean, const float* __restrict__ bn_var,
                        const float* __restrict__ in_W, const float* __restrict__ in_b,
                        const float* __restrict__ lin_W) {
    int b = blockIdx.x;
    int t = threadIdx.x;
    if (b >= 4) {
        int idx = (b - 4) * 128 + t;
        if (idx < NN) g_cnt[idx] = 0;
        return;
    }
    __shared__ float ss[FF], st[FF];
    if (t < FF) {
        float sv = bn_w[t] * rsqrtf(bn_var[t] + 1e-5f);
        ss[t] = sv;
        st[t] = bn_b[t] - bn_mean[t] * sv;
    }
    __syncthreads();
    for (int idx = t; idx < 32 * CC; idx += blockDim.x) {
        int k = b * 32 + idx / CC, c = idx % CC;
        g_WTin[k * CC + c] = in_W[c * FF + k] * ss[k];
    }
    for (int idx = t; idx < CC * CC; idx += blockDim.x) {
        int k = idx / CC, c = idx % CC;
        g_WT[(b * CC + k) * CC + c] = lin_W[(b * CC + c) * CC + k];
    }
    if (b == 0 && t < CC) {
        float acc = in_b[t];
        for (int k = 0; k < FF; k++) acc += in_W[t * FF + k] * st[k];
        g_bp[t] = acc;
    }
}

// ---------------- GEMM body: 128 thr, 128x64 tile, 8x8 micro, W prefetched ---
template <int K, int MODE>
__device__ __forceinline__ void gemm_body(int bid,
                       const float* __restrict__ ext_in,
                       int layer,
                       const float* __restrict__ bext,
                       const float* __restrict__ gn_w_l,
                       const float* __restrict__ gn_b_l,
                       const float* __restrict__ gn_ms_l) {
    extern __shared__ float smem[];
    float* sX = smem;
    float* sW = smem + NT * SXS;
    __shared__ float sb[CC], s_sub[CC], s_scl[CC], s_off[CC];
    int t = threadIdx.x;
    if (t < CC) sb[t] = (MODE == 0) ? g_bp[t] : bext[t];
    if (MODE == 2 && t < CC) {
        double mu = (double)g_stat[t] / (double)NN;
        double g = (double)gn_ms_l[t];
        double var = (double)g_stat[64 + t] / (double)NN - (2.0 * g - g * g) * mu * mu;
        float rstd = (float)(1.0 / sqrt(var + 1e-5));
        s_sub[t] = (float)(g * mu);
        s_scl[t] = gn_w_l[t] * rstd;
        s_off[t] = gn_b_l[t];
    }
    __syncthreads();

    const float* xin = (MODE == 0) ? ext_in : (MODE == 1 ? (const float*)g_h
                                                         : (const float*)g_hraw);
    const float* WT = (MODE == 0) ? (const float*)g_WTin
                                  : (const float*)(g_WT + layer * CC * CC);
    int base = bid * NT;
    int tx = t & 7, ty = t >> 3;

    unsigned long long acc[8][4];
#pragma unroll
    for (int i = 0; i < 8; i++)
#pragma unroll
        for (int j = 0; j < 4; j++) acc[i][j] = 0ull;

    const int NCHUNK = K / 64;
    for (int kc = 0; kc < NCHUNK; kc++) {
#pragma unroll
        for (int j = 0; j < 16; j++) {
            int idx = t + j * GBT;
            int node = idx >> 4, kq = idx & 15;
            int gn = base + node;
            float4 v = make_float4(0.f, 0.f, 0.f, 0.f);
            if (gn < NN)
                v = *(const float4*)(xin + (size_t)gn * K + kc * 64 + kq * 4);
            if (MODE == 2) {
                int c = kq * 4;
                v.x = lrelu((v.x - s_sub[c + 0]) * s_scl[c + 0] + s_off[c + 0], 0.01f);
                v.y = lrelu((v.y - s_sub[c + 1]) * s_scl[c + 1] + s_off[c + 1], 0.01f);
                v.z = lrelu((v.z - s_sub[c + 2]) * s_scl[c + 2] + s_off[c + 2], 0.01f);
                v.w = lrelu((v.w - s_sub[c + 3]) * s_scl[c + 3] + s_off[c + 3], 0.01f);
            }
            *(float4*)&sX[node * SXS + kq * 4] = v;
        }
#pragma unroll
        for (int j = 0; j < 8; j++) {
            int idx = t + j * GBT;
            ((float4*)sW)[idx] = ((const float4*)(WT + kc * 64 * CC))[idx];
        }
        __syncthreads();

        // preload W pair for kq=0 (prefetch pipeline: W one k-pair ahead)
        ulonglong2 wa0 = *(const ulonglong2*)&sW[0 * 64 + tx * 8];
        ulonglong2 wb0 = *(const ulonglong2*)&sW[0 * 64 + tx * 8 + 4];
        ulonglong2 wa1 = *(const ulonglong2*)&sW[1 * 64 + tx * 8];
        ulonglong2 wb1 = *(const ulonglong2*)&sW[1 * 64 + tx * 8 + 4];

        for (int kq = 0; kq < 64; kq += 2) {
            // x loads for this k-pair (first use ~12 issue slots later)
            float2 xv[8];
#pragma unroll
            for (int i = 0; i < 8; i++)
                xv[i] = *(const float2*)&sX[(ty + i * 16) * SXS + kq];
            // prefetch next W pair
            ulonglong2 na0, nb0, na1, nb1;
            if (kq + 2 < 64) {
                na0 = *(const ulonglong2*)&sW[(kq + 2) * 64 + tx * 8];
                nb0 = *(const ulonglong2*)&sW[(kq + 2) * 64 + tx * 8 + 4];
                na1 = *(const ulonglong2*)&sW[(kq + 3) * 64 + tx * 8];
                nb1 = *(const ulonglong2*)&sW[(kq + 3) * 64 + tx * 8 + 4];
            }
#pragma unroll
            for (int i = 0; i < 8; i++) {
                unsigned long long xp = pack2(xv[i].x);
                ffma2(acc[i][0], xp, wa0.x);
                ffma2(acc[i][1], xp, wa0.y);
                ffma2(acc[i][2], xp, wb0.x);
                ffma2(acc[i][3], xp, wb0.y);
            }
#pragma unroll
            for (int i = 0; i < 8; i++) {
                unsigned long long xp = pack2(xv[i].y);
                ffma2(acc[i][0], xp, wa1.x);
                ffma2(acc[i][1], xp, wa1.y);
                ffma2(acc[i][2], xp, wb1.x);
                ffma2(acc[i][3], xp, wb1.y);
            }
            if (kq + 2 < 64) {
                wa0 = na0; wb0 = nb0; wa1 = na1; wb1 = nb1;
            }
        }
        if (kc + 1 < NCHUNK) __syncthreads();
    }

    float4 b0 = *(const float4*)&sb[tx * 8];
    float4 b1 = *(const float4*)&sb[tx * 8 + 4];
    float* outp = (MODE == 0) ? g_h : g_z;
#pragma unroll
    for (int i = 0; i < 8; i++) {
        int node = base + ty + i * 16;
        if (node >= NN) continue;
        float4 r0, r1;
        unpack2(acc[i][0], r0.x, r0.y);
        unpack2(acc[i][1], r0.z, r0.w);
        unpack2(acc[i][2], r1.x, r1.y);
        unpack2(acc[i][3], r1.z, r1.w);
        r0.x += b0.x; r0.y += b0.y; r0.z += b0.z; r0.w += b0.w;
        r1.x += b1.x; r1.y += b1.y; r1.z += b1.z; r1.w += b1.w;
        if (MODE == 0) {
            r0.x = lrelu(r0.x, 0.01f); r0.y = lrelu(r0.y, 0.01f);
            r0.z = lrelu(r0.z, 0.01f); r0.w = lrelu(r0.w, 0.01f);
            r1.x = lrelu(r1.x, 0.01f); r1.y = lrelu(r1.y, 0.01f);
            r1.z = lrelu(r1.z, 0.01f); r1.w = lrelu(r1.w, 0.01f);
        }
        float* op = outp + (size_t)node * CC + tx * 8;
        *(float4*)op = r0;
        *(float4*)(op + 4) = r1;
    }
}

// ---------------- fat kernels ------------------------------------------------
__global__ void __launch_bounds__(GBT, 4) k_fat1(const float* __restrict__ x,
                                                 const int* __restrict__ dst) {
    if (blockIdx.x < GB) {
        gemm_body<FF, 0>(blockIdx.x, x, 0, nullptr, nullptr, nullptr, nullptr);
    } else {
        int i = (blockIdx.x - GB) * GBT + threadIdx.x;
        if (i < EP) {
            int d = i < EE ? dst[i] : i - EE;
            atomicAdd(&g_cnt[d], 1);
        }
    }
}

__global__ void __launch_bounds__(GBT, 4) k_fat2(const float* __restrict__ lin_b) {
    if (blockIdx.x < GB) {
        gemm_body<CC, 1>(blockIdx.x, nullptr, 0, lin_b, nullptr, nullptr, nullptr);
        return;
    }
    int b = blockIdx.x - GB;
    int t = threadIdx.x;
    int base = b * 1024;
    int loc[8];
    int run = 0;
#pragma unroll
    for (int j = 0; j < 8; j++) {
        int i = base + t * 8 + j;
        int v = (i < NN) ? g_cnt[i] : 0;
        run += v;
        loc[j] = run;
    }
    __shared__ int sT[128];
    sT[t] = run;
    __syncthreads();
    for (int off = 1; off < 128; off <<= 1) {
        int add = (t >= off) ? sT[t - off] : 0;
        __syncthreads();
        sT[t] += add;
        __syncthreads();
    }
    int excl = sT[t] - run;
#pragma unroll
    for (int j = 0; j < 8; j++) {
        int i = base + t * 8 + j;
        if (i < NN) g_cur[i] = excl + loc[j];
    }
    if (t == 127) g_bsum[b] = sT[127];
}

__global__ void k_scan3() {
    __shared__ int sv[128];
    __shared__ int sOff;
    int t = threadIdx.x;
    int b = blockIdx.x;
    sv[t] = (t < b) ? g_bsum[t] : 0;
    __syncthreads();
    for (int off = 64; off >= 1; off >>= 1) {
        if (t < off) sv[t] += sv[t + off];
        __syncthreads();
    }
    if (t == 0) sOff = sv[0];
    __syncthreads();
    int boff = sOff;
    int base = b * 1024;
#pragma unroll
    for (int j = 0; j < 8; j++) {
        int i = base + t * 8 + j;
        if (i < NN) {
            int incl = g_cur[i];
            int ex = incl - g_cnt[i] + boff;
            g_offs[i] = ex;
            g_cur[i] = ex;
            if (i == NN - 1) g_offs[NN] = incl + boff;
        }
    }
}

__global__ void k_scatter(const int* __restrict__ dst) {
    int i = blockIdx.x * blockDim.x + threadIdx.x;
    if (i >= EP) return;
    int d = i < EE ? dst[i] : i - EE;
    int pos = atomicAdd(&g_cur[d], 1);
    g_elist[pos] = i;
}

// ---------------- edge pass (fused segment sort on layer 0) ------------------
template <bool SORT>
__global__ void k_edge(const int* __restrict__ src,
                       const float* __restrict__ att_l,
                       const float* __restrict__ cb_l,
                       float* __restrict__ alpha_out) {
    const unsigned FULL = 0xffffffffu;
    int warp = (blockIdx.x * blockDim.x + threadIdx.x) >> 5;
    int lane = threadIdx.x & 31;
    if (warp >= NN) return;
    int n = warp;
    int g = lane >> 3, cl = lane & 7;

    int beg = g_offs[n], end = g_offs[n + 1];

    if (SORT) {
        int d = end - beg;
        if (d > 1) {
            if (d <= 32) {
                int key = (beg + lane < end) ? g_elist[beg + lane] : 0x7fffffff;
#pragma unroll
                for (int ph = 0; ph < 32; ph++) {
                    int odd = ph & 1;
                    bool lo = (((lane ^ odd) & 1) == 0);
                    int partner = lo ? lane + 1 : lane - 1;
                    int pv = __shfl_sync(FULL, key, partner & 31);
                    if (partner >= 0 && partner < 32)
                        key = lo ? min(key, pv) : max(key, pv);
                }
                if (lane < d) g_elist[beg + lane] = key;
            } else if (lane == 0) {
                for (int i = beg + 1; i < end; i++) {
                    int key = g_elist[i];
                    int j = i - 1;
                    while (j >= beg && g_elist[j] > key) { g_elist[j + 1] = g_elist[j]; j--; }
                    g_elist[j + 1] = key;
                }
            }
            __syncwarp();
        }
    }

    const float4* z4 = reinterpret_cast<const float4*>(g_z);
    float4 zd0 = z4[(size_t)n * 16 + cl * 2];
    float4 zd1 = z4[(size_t)n * 16 + cl * 2 + 1];
    float4 at0 = reinterpret_cast<const float4*>(att_l)[cl * 2];
    float4 at1 = reinterpret_cast<const float4*>(att_l)[cl * 2 + 1];

    float m = -1e30f, den = 0.f;
    float4 acc0 = {0, 0, 0, 0}, acc1 = {0, 0, 0, 0};

    for (int cs = beg; cs < end; cs += 32) {
        int p32 = cs + lane;
        int s = n;
        if (p32 < end) {
            int e = g_elist[p32];
            s = (e < EE) ? src[e] : (e - EE);
        }
        int nchunk = min(8, (end - cs + 3) >> 2);
        int sv = __shfl_sync(FULL, s, g);
        float4 zs0 = z4[(size_t)sv * 16 + cl * 2];
        float4 zs1 = z4[(size_t)sv * 16 + cl * 2 + 1];
        for (int it = 0; it < nchunk; it++) {
            int pidx = cs + it * 4 + g;
            bool valid = pidx < end;
            float4 nz0 = zs0, nz1 = zs1;
            if (it + 1 < nchunk) {
                int sv2 = __shfl_sync(FULL, s, (it + 1) * 4 + g);
                nz0 = z4[(size_t)sv2 * 16 + cl * 2];
                nz1 = z4[(size_t)sv2 * 16 + cl * 2 + 1];
            }
            float part =
                lrelu(zs0.x + zd0.x, 0.2f) * at0.x + lrelu(zs0.y + zd0.y, 0.2f) * at0.y +
                lrelu(zs0.z + zd0.z, 0.2f) * at0.z + lrelu(zs0.w + zd0.w, 0.2f) * at0.w +
                lrelu(zs1.x + zd1.x, 0.2f) * at1.x + lrelu(zs1.y + zd1.y, 0.2f) * at1.y +
                lrelu(zs1.z + zd1.z, 0.2f) * at1.z + lrelu(zs1.w + zd1.w, 0.2f) * at1.w;
            part += __shfl_xor_sync(FULL, part, 4);
            part += __shfl_xor_sync(FULL, part, 2);
            part += __shfl_xor_sync(FULL, part, 1);
            float score = valid ? part : -1e30f;
            if (valid && cl == 0) g_score[pidx] = score;
            float nm = fmaxf(m, score);
            float sc = __expf(m - nm);
            float w = __expf(score - nm);
            den = den * sc + w;
            acc0.x = acc0.x * sc + w * zs0.x; acc0.y = acc0.y * sc + w * zs0.y;
            acc0.z = acc0.z * sc + w * zs0.z; acc0.w = acc0.w * sc + w * zs0.w;
            acc1.x = acc1.x * sc + w * zs1.x; acc1.y = acc1.y * sc + w * zs1.y;
            acc1.z = acc1.z * sc + w * zs1.z; acc1.w = acc1.w * sc + w * zs1.w;
            m = nm;
            zs0 = nz0; zs1 = nz1;
        }
    }

    float M = fmaxf(m, __shfl_xor_sync(FULL, m, 8));
    M = fmaxf(M, __shfl_xor_sync(FULL, M, 16));
    float f = __expf(m - M);
    den *= f;
    acc0.x *= f; acc0.y *= f; acc0.z *= f; acc0.w *= f;
    acc1.x *= f; acc1.y *= f; acc1.z *= f; acc1.w *= f;
    den += __shfl_xor_sync(FULL, den, 8);
    den += __shfl_xor_sync(FULL, den, 16);
#pragma unroll
    for (int off = 8; off <= 16; off <<= 1) {
        acc0.x += __shfl_xor_sync(FULL, acc0.x, off);
        acc0.y += __shfl_xor_sync(FULL, acc0.y, off);
        acc0.z += __shfl_xor_sync(FULL, acc0.z, off);
        acc0.w += __shfl_xor_sync(FULL, acc0.w, off);
        acc1.x += __shfl_xor_sync(FULL, acc1.x, off);
        acc1.y += __shfl_xor_sync(FULL, acc1.y, off);
        acc1.z += __shfl_xor_sync(FULL, acc1.z, off);
        acc1.w += __shfl_xor_sync(FULL, acc1.w, off);
    }
    float invd = 1.f / (den + 1e-16f);
    if (g == 0) {
        float4 cb0 = reinterpret_cast<const float4*>(cb_l)[cl * 2];
        float4 cb1 = reinterpret_cast<const float4*>(cb_l)[cl * 2 + 1];
        float4 o0, o1;
        o0.x = acc0.x * invd + cb0.x; o0.y = acc0.y * invd + cb0.y;
        o0.z = acc0.z * invd + cb0.z; o0.w = acc0.w * invd + cb0.w;
        o1.x = acc1.x * invd + cb1.x; o1.y = acc1.y * invd + cb1.y;
        o1.z = acc1.z * invd + cb1.z; o1.w = acc1.w * invd + cb1.w;
        float4* hr = reinterpret_cast<float4*>(g_hraw);
        hr[(size_t)n * 16 + cl * 2] = o0;
        hr[(size_t)n * 16 + cl * 2 + 1] = o1;
    }
    __syncwarp();
    for (int p = beg + lane; p < end; p += 32) {
        alpha_out[g_elist[p]] = __expf(g_score[p] - M) * invd;
    }
}

// ---------------- GEMM MODE2 standalone --------------------------------------
__global__ void __launch_bounds__(GBT, 4) k_gemm2(int layer,
                       const float* __restrict__ bext,
                       const float* __restrict__ gn_w_l,
                       const float* __restrict__ gn_b_l,
                       const float* __restrict__ gn_ms_l) {
    gemm_body<CC, 2>(blockIdx.x, nullptr, layer, bext, gn_w_l, gn_b_l, gn_ms_l);
}

// ---------------- fused GraphNorm stats --------------------------------------
__global__ void k_redF() {
    int t = threadIdx.x;
    int gid = blockIdx.x * blockDim.x + t;
    const int stride = RBLK * 256;
    float a1[4] = {0, 0, 0, 0}, a2[4] = {0, 0, 0, 0};
    const float4* hr = (const float4*)g_hraw;
    for (int i = gid; i < NN * CC / 4; i += stride) {
        float4 v = hr[i];
        a1[0] += v.x; a2[0] += v.x * v.x;
        a1[1] += v.y; a2[1] += v.y * v.y;
        a1[2] += v.z; a2[2] += v.z * v.z;
        a1[3] += v.w; a2[3] += v.w * v.w;
    }
    __shared__ float sh[256 * 8];
#pragma unroll
    for (int q = 0; q < 4; q++) { sh[t * 8 + q] = a1[q]; sh[t * 8 + 4 + q] = a2[q]; }
    __syncthreads();
    if (t < 16) {
        int c0 = (4 * gid) & 63;
        float r1[4] = {0, 0, 0, 0}, r2[4] = {0, 0, 0, 0};
        for (int j = t; j < 256; j += 16) {
#pragma unroll
            for (int q = 0; q < 4; q++) {
                r1[q] += sh[j * 8 + q];
                r2[q] += sh[j * 8 + 4 + q];
            }
        }
#pragma unroll
        for (int q = 0; q < 4; q++) {
            g_part[blockIdx.x * 128 + c0 + q] = r1[q];
            g_part[blockIdx.x * 128 + 64 + c0 + q] = r2[q];
        }
    }
    __threadfence();
    __shared__ int s_last;
    __shared__ float s_half[2][128];
    if (t == 0) s_last = (atomicAdd(&g_rc, 1) == RBLK - 1) ? 1 : 0;
    __syncthreads();
    if (s_last) {
        int ch = t & 127;
        int b0 = (t < 128) ? 0 : RBLK / 2;
        float s0 = 0.f, s1 = 0.f, s2 = 0.f, s3 = 0.f;
        for (int b = b0; b < b0 + RBLK / 2; b += 4) {
            s0 += g_part[(b + 0) * 128 + ch];
            s1 += g_part[(b + 1) * 128 + ch];
            s2 += g_part[(b + 2) * 128 + ch];
            s3 += g_part[(b + 3) * 128 + ch];
        }
        s_half[t >> 7][ch] = (s0 + s1) + (s2 + s3);
        __syncthreads();
        if (t < 128) g_stat[t] = s_half[0][t] + s_half[1][t];
        __syncthreads();
        if (t == 0) g_rc = 0;
    }
}

__global__ void k_norm_last(const float* __restrict__ gn_w_l,
                            const float* __restrict__ gn_b_l,
                            const float* __restrict__ gn_ms_l,
                            float* __restrict__ out) {
    __shared__ float s_sub[CC], s_w[CC], s_b[CC];
    int t = threadIdx.x;
    if (t < CC) {
        double mu = (double)g_stat[t] / (double)NN;
        double g = (double)gn_ms_l[t];
        double var = (double)g_stat[64 + t] / (double)NN - (2.0 * g - g * g) * mu * mu;
        float rstd = (float)(1.0 / sqrt(var + 1e-5));
        s_sub[t] = (float)(g * mu);
        s_w[t] = gn_w_l[t] * rstd;
        s_b[t] = gn_b_l[t];
    }
    __syncthreads();
    int gid = blockIdx.x * blockDim.x + t;
    const int stride = 2048 * 256;
    const float4* hr = (const float4*)g_hraw;
    float4* o0 = (float4*)out;
    float4* o1 = (float4*)(out + NN * CC);
    for (int i = gid; i < NN * CC / 4; i += stride) {
        int c = (4 * i) & 63;
        float4 v = hr[i];
        v.x = lrelu((v.x - s_sub[c + 0]) * s_w[c + 0] + s_b[c + 0], 0.01f);
        v.y = lrelu((v.y - s_sub[c + 1]) * s_w[c + 1] + s_b[c + 1], 0.01f);
        v.z = lrelu((v.z - s_sub[c + 2]) * s_w[c + 2] + s_b[c + 2], 0.01f);
        v.w = lrelu((v.w - s_sub[c + 3]) * s_w[c + 3] + s_b[c + 3], 0.01f);
        o0[i] = v;
        o1[i] = v;
    }
}

extern "C" void kernel_launch(void* const* d_in, const int* in_sizes, int n_in,
                              void* d_out, int out_size) {
    (void)in_sizes; (void)n_in; (void)out_size;
    const float* x       = (const float*)d_in[0];
    const int*   src     = (const int*)d_in[1];
    const int*   dst     = (const int*)d_in[2];
    const float* bn_w    = (const float*)d_in[3];
    const float* bn_b    = (const float*)d_in[4];
    const float* bn_mean = (const float*)d_in[5];
    const float* bn_var  = (const float*)d_in[6];
    const float* in_W    = (const float*)d_in[7];
    const float* in_b    = (const float*)d_in[8];
    const float* lin_W   = (const float*)d_in[9];
    const float* lin_b   = (const float*)d_in[10];
    const float* att     = (const float*)d_in[11];
    const float* conv_b  = (const float*)d_in[12];
    const float* gn_w    = (const float*)d_in[13];
    const float* gn_b    = (const float*)d_in[14];
    const float* gn_ms   = (const float*)d_in[15];
    float* out = (float*)d_out;

    static bool attr_done = false;
    if (!attr_done) {
        cudaFuncSetAttribute(k_fat1, cudaFuncAttributeMaxDynamicSharedMemorySize, GEMM_SMEM);
        cudaFuncSetAttribute(k_fat2, cudaFuncAttributeMaxDynamicSharedMemorySize, GEMM_SMEM);
        cudaFuncSetAttribute(k_gemm2, cudaFuncAttributeMaxDynamicSharedMemorySize, GEMM_SMEM);
        attr_done = true;
    }

    const int SETUP_B = 4 + (NN + 127) / 128;
    const int HIST_B = (EP + GBT - 1) / GBT;

    k_setup<<<SETUP_B, 128>>>(bn_w, bn_b, bn_mean, bn_var, in_W, in_b, lin_W);  // 0
    k_fat1<<<GB + HIST_B, GBT, GEMM_SMEM>>>(x, dst);                            // 1
    k_fat2<<<GB + NB1, GBT, GEMM_SMEM>>>(lin_b);                                // 2
    k_scan3<<<NB1, 128>>>();                                                    // 3
    k_scatter<<<(EP + 255) / 256, 256>>>(dst);                                  // 4

    for (int l = 0; l < LL; l++) {
        if (l > 0) {
            k_gemm2<<<GB, GBT, GEMM_SMEM>>>(l, lin_b + l * CC,
                                            gn_w + (l - 1) * CC, gn_b + (l - 1) * CC,
                                            gn_ms + (l - 1) * CC);
        }
        if (l == 0)
            k_edge<true><<<(NN * 32 + 255) / 256, 256>>>(src, att, conv_b,
                                                         out + 2 * NN * CC);
        else
            k_edge<false><<<(NN * 32 + 255) / 256, 256>>>(src, att + l * CC, conv_b + l * CC,
                                                          out + 2 * NN * CC + l * EP);
        k_redF<<<RBLK, 256>>>();
    }
    k_norm_last<<<2048, 256>>>(gn_w + 3 * CC, gn_b + 3 * CC, gn_ms + 3 * CC, out);
}

// round 14
// speedup vs baseline: 1.0107x; 1.0107x over previous
#include <cuda_runtime.h>
#include <math.h>

#define NN 100000
#define EE 1000000
#define EP (EE + NN)
#define FF 128
#define CC 64
#define LL 4
#define NB1 98
#define RBLK 512
#define GBT 128
#define NT 128
#define SXS 68
#define GEMM_SMEM ((NT * SXS + 64 * 64) * 4)
#define GB ((NN + NT - 1) / NT)

__device__ float  g_h[NN * CC];
__device__ float  g_z[NN * CC];
__device__ float  g_hraw[NN * CC];
__device__ float  g_score[EP];
__device__ int    g_cnt[NN];          // zero-init at load; re-zeroed by k_scan3
__device__ int    g_offs[NN + 1];
__device__ int    g_cur[NN];
__device__ int    g_elist[EP];
__device__ int    g_bsum[NB1 + 2];
__device__ float  g_part[RBLK * 128];
__device__ float  g_stat[128];
__device__ float  g_WTin[FF * CC];
__device__ float  g_WT[LL * CC * CC];
__device__ float  g_bp[CC];
__device__ int    g_rc = 0;

__device__ __forceinline__ float lrelu(float v, float s) { return v >= 0.f ? v : s * v; }

__device__ __forceinline__ void ffma2(unsigned long long &d, unsigned long long a,
                                      unsigned long long b) {
    asm("fma.rn.f32x2 %0, %1, %2, %0;" : "+l"(d) : "l"(a), "l"(b));
}
__device__ __forceinline__ unsigned long long pack2(float x) {
    unsigned long long r;
    unsigned int xi = __float_as_uint(x);
    asm("mov.b64 %0, {%1, %1};" : "=l"(r) : "r"(xi));
    return r;
}
__device__ __forceinline__ void unpack2(unsigned long long v, float &lo, float &hi) {
    unsigned int a, b;
    asm("mov.b64 {%0, %1}, %2;" : "=r"(a), "=r"(b) : "l"(v));
    lo = __uint_as_float(a); hi = __uint_as_float(b);
}

// ---------------- setup (weights only; g_cnt zeroed by scan3 each replay) ----
__global__ void k_setup(const float* __restrict__ bn_w, const float* __restrict__ bn_b,
                        const float* __restrict__ bn_mean, const float* __restrict__ bn_var,
                        const float* __restrict__ in_W, const float* __restrict__ in_b,
                        const float* __restrict__ lin_W) {
    int b = blockIdx.x;
    int t = threadIdx.x;
    __shared__ float ss[FF], st[FF];
    if (t < FF) {
        float sv = bn_w[t] * rsqrtf(bn_var[t] + 1e-5f);
        ss[t] = sv;
        st[t] = bn_b[t] - bn_mean[t] * sv;
    }
    __syncthreads();
    for (int idx = t; idx < 32 * CC; idx += blockDim.x) {
        int k = b * 32 + idx / CC, c = idx % CC;
        g_WTin[k * CC + c] = in_W[c * FF + k] * ss[k];
    }
    for (int idx = t; idx < CC * CC; idx += blockDim.x) {
        int k = idx / CC, c = idx % CC;
        g_WT[(b * CC + k) * CC + c] = lin_W[(b * CC + c) * CC + k];
    }
    if (b == 0 && t < CC) {
        float acc = in_b[t];
        for (int k = 0; k < FF; k++) acc += in_W[t * FF + k] * st[k];
        g_bp[t] = acc;
    }
}

// ---------------- GEMM body (R12-proven: 128 thr, x-prefetch schedule) -------
template <int K, int MODE>
__device__ __forceinline__ void gemm_body(int bid,
                       const float* __restrict__ ext_in,
                       int layer,
                       const float* __restrict__ bext,
                       const float* __restrict__ gn_w_l,
                       const float* __restrict__ gn_b_l,
                       const float* __restrict__ gn_ms_l) {
    extern __shared__ float smem[];
    float* sX = smem;
    float* sW = smem + NT * SXS;
    __shared__ float sb[CC], s_sub[CC], s_scl[CC], s_off[CC];
    int t = threadIdx.x;
    if (t < CC) sb[t] = (MODE == 0) ? g_bp[t] : bext[t];
    if (MODE == 2 && t < CC) {
        double mu = (double)g_stat[t] / (double)NN;
        double g = (double)gn_ms_l[t];
        double var = (double)g_stat[64 + t] / (double)NN - (2.0 * g - g * g) * mu * mu;
        float rstd = (float)(1.0 / sqrt(var + 1e-5));
        s_sub[t] = (float)(g * mu);
        s_scl[t] = gn_w_l[t] * rstd;
        s_off[t] = gn_b_l[t];
    }
    __syncthreads();

    const float* xin = (MODE == 0) ? ext_in : (MODE == 1 ? (const float*)g_h
                                                         : (const float*)g_hraw);
    const float* WT = (MODE == 0) ? (const float*)g_WTin
                                  : (const float*)(g_WT + layer * CC * CC);
    int base = bid * NT;
    int tx = t & 7, ty = t >> 3;

    unsigned long long acc[8][4];
#pragma unroll
    for (int i = 0; i < 8; i++)
#pragma unroll
        for (int j = 0; j < 4; j++) acc[i][j] = 0ull;

    const int NCHUNK = K / 64;
    for (int kc = 0; kc < NCHUNK; kc++) {
#pragma unroll
        for (int j = 0; j < 16; j++) {
            int idx = t + j * GBT;
            int node = idx >> 4, kq = idx & 15;
            int gn = base + node;
            float4 v = make_float4(0.f, 0.f, 0.f, 0.f);
            if (gn < NN)
                v = *(const float4*)(xin + (size_t)gn * K + kc * 64 + kq * 4);
            if (MODE == 2) {
                int c = kq * 4;
                v.x = lrelu((v.x - s_sub[c + 0]) * s_scl[c + 0] + s_off[c + 0], 0.01f);
                v.y = lrelu((v.y - s_sub[c + 1]) * s_scl[c + 1] + s_off[c + 1], 0.01f);
                v.z = lrelu((v.z - s_sub[c + 2]) * s_scl[c + 2] + s_off[c + 2], 0.01f);
                v.w = lrelu((v.w - s_sub[c + 3]) * s_scl[c + 3] + s_off[c + 3], 0.01f);
            }
            *(float4*)&sX[node * SXS + kq * 4] = v;
        }
#pragma unroll
        for (int j = 0; j < 8; j++) {
            int idx = t + j * GBT;
            ((float4*)sW)[idx] = ((const float4*)(WT + kc * 64 * CC))[idx];
        }
        __syncthreads();

        float2 xv[8];
#pragma unroll
        for (int i = 0; i < 8; i++)
            xv[i] = *(const float2*)&sX[(ty + i * 16) * SXS + 0];

        for (int kq = 0; kq < 64; kq += 2) {
            ulonglong2 wa0 = *(const ulonglong2*)&sW[kq * 64 + tx * 8];
            ulonglong2 wb0 = *(const ulonglong2*)&sW[kq * 64 + tx * 8 + 4];
            ulonglong2 wa1 = *(const ulonglong2*)&sW[(kq + 1) * 64 + tx * 8];
            ulonglong2 wb1 = *(const ulonglong2*)&sW[(kq + 1) * 64 + tx * 8 + 4];
            float2 xn[8];
            if (kq + 2 < 64) {
#pragma unroll
                for (int i = 0; i < 8; i++)
                    xn[i] = *(const float2*)&sX[(ty + i * 16) * SXS + kq + 2];
            }
#pragma unroll
            for (int i = 0; i < 8; i++) {
                unsigned long long xp = pack2(xv[i].x);
                ffma2(acc[i][0], xp, wa0.x);
                ffma2(acc[i][1], xp, wa0.y);
                ffma2(acc[i][2], xp, wb0.x);
                ffma2(acc[i][3], xp, wb0.y);
            }
#pragma unroll
            for (int i = 0; i < 8; i++) {
                unsigned long long xp = pack2(xv[i].y);
                ffma2(acc[i][0], xp, wa1.x);
                ffma2(acc[i][1], xp, wa1.y);
                ffma2(acc[i][2], xp, wb1.x);
                ffma2(acc[i][3], xp, wb1.y);
            }
            if (kq + 2 < 64) {
#pragma unroll
                for (int i = 0; i < 8; i++) xv[i] = xn[i];
            }
        }
        if (kc + 1 < NCHUNK) __syncthreads();
    }

    float4 b0 = *(const float4*)&sb[tx * 8];
    float4 b1 = *(const float4*)&sb[tx * 8 + 4];
    float* outp = (MODE == 0) ? g_h : g_z;
#pragma unroll
    for (int i = 0; i < 8; i++) {
        int node = base + ty + i * 16;
        if (node >= NN) continue;
        float4 r0, r1;
        unpack2(acc[i][0], r0.x, r0.y);
        unpack2(acc[i][1], r0.z, r0.w);
        unpack2(acc[i][2], r1.x, r1.y);
        unpack2(acc[i][3], r1.z, r1.w);
        r0.x += b0.x; r0.y += b0.y; r0.z += b0.z; r0.w += b0.w;
        r1.x += b1.x; r1.y += b1.y; r1.z += b1.z; r1.w += b1.w;
        if (MODE == 0) {
            r0.x = lrelu(r0.x, 0.01f); r0.y = lrelu(r0.y, 0.01f);
            r0.z = lrelu(r0.z, 0.01f); r0.w = lrelu(r0.w, 0.01f);
            r1.x = lrelu(r1.x, 0.01f); r1.y = lrelu(r1.y, 0.01f);
            r1.z = lrelu(r1.z, 0.01f); r1.w = lrelu(r1.w, 0.01f);
        }
        float* op = outp + (size_t)node * CC + tx * 8;
        *(float4*)op = r0;
        *(float4*)(op + 4) = r1;
    }
}

// ---------------- fat kernels ------------------------------------------------
__global__ void __launch_bounds__(GBT, 4) k_fat1(const float* __restrict__ x,
                                                 const int* __restrict__ dst) {
    if (blockIdx.x < GB) {
        gemm_body<FF, 0>(blockIdx.x, x, 0, nullptr, nullptr, nullptr, nullptr);
    } else {
        int i = (blockIdx.x - GB) * GBT + threadIdx.x;
        if (i < EP) {
            int d = i < EE ? dst[i] : i - EE;
            atomicAdd(&g_cnt[d], 1);
        }
    }
}

__global__ void __launch_bounds__(GBT, 4) k_fat2(const float* __restrict__ lin_b) {
    if (blockIdx.x < GB) {
        gemm_body<CC, 1>(blockIdx.x, nullptr, 0, lin_b, nullptr, nullptr, nullptr);
        return;
    }
    int b = blockIdx.x - GB;
    int t = threadIdx.x;
    int base = b * 1024;
    int loc[8];
    int run = 0;
#pragma unroll
    for (int j = 0; j < 8; j++) {
        int i = base + t * 8 + j;
        int v = (i < NN) ? g_cnt[i] : 0;
        run += v;
        loc[j] = run;
    }
    __shared__ int sT[128];
    sT[t] = run;
    __syncthreads();
    for (int off = 1; off < 128; off <<= 1) {
        int add = (t >= off) ? sT[t - off] : 0;
        __syncthreads();
        sT[t] += add;
        __syncthreads();
    }
    int excl = sT[t] - run;
#pragma unroll
    for (int j = 0; j < 8; j++) {
        int i = base + t * 8 + j;
        if (i < NN) g_cur[i] = excl + loc[j];
    }
    if (t == 127) g_bsum[b] = sT[127];
}

// scan3: add cross-block offsets; also re-zeroes g_cnt (last reader) so the
// next graph replay starts from a clean histogram without a setup pass.
__global__ void k_scan3() {
    __shared__ int sv[128];
    __shared__ int sOff;
    int t = threadIdx.x;
    int b = blockIdx.x;
    sv[t] = (t < b) ? g_bsum[t] : 0;
    __syncthreads();
    for (int off = 64; off >= 1; off >>= 1) {
        if (t < off) sv[t] += sv[t + off];
        __syncthreads();
    }
    if (t == 0) sOff = sv[0];
    __syncthreads();
    int boff = sOff;
    int base = b * 1024;
#pragma unroll
    for (int j = 0; j < 8; j++) {
        int i = base + t * 8 + j;
        if (i < NN) {
            int incl = g_cur[i];
            int ex = incl - g_cnt[i] + boff;
            g_cnt[i] = 0;                     // reset for next replay
            g_offs[i] = ex;
            g_cur[i] = ex;
            if (i == NN - 1) g_offs[NN] = incl + boff;
        }
    }
}

__global__ void k_scatter(const int* __restrict__ dst) {
    int i = blockIdx.x * blockDim.x + threadIdx.x;
    if (i >= EP) return;
    int d = i < EE ? dst[i] : i - EE;
    int pos = atomicAdd(&g_cur[d], 1);
    g_elist[pos] = i;
}

// ---------------- edge pass (fused segment sort on layer 0) ------------------
template <bool SORT>
__global__ void k_edge(const int* __restrict__ src,
                       const float* __restrict__ att_l,
                       const float* __restrict__ cb_l,
                       float* __restrict__ alpha_out) {
    const unsigned FULL = 0xffffffffu;
    int warp = (blockIdx.x * blockDim.x + threadIdx.x) >> 5;
    int lane = threadIdx.x & 31;
    if (warp >= NN) return;
    int n = warp;
    int g = lane >> 3, cl = lane & 7;

    int beg = g_offs[n], end = g_offs[n + 1];

    if (SORT) {
        int d = end - beg;
        if (d > 1) {
            if (d <= 32) {
                int key = (beg + lane < end) ? g_elist[beg + lane] : 0x7fffffff;
#pragma unroll
                for (int ph = 0; ph < 32; ph++) {
                    int odd = ph & 1;
                    bool lo = (((lane ^ odd) & 1) == 0);
                    int partner = lo ? lane + 1 : lane - 1;
                    int pv = __shfl_sync(FULL, key, partner & 31);
                    if (partner >= 0 && partner < 32)
                        key = lo ? min(key, pv) : max(key, pv);
                }
                if (lane < d) g_elist[beg + lane] = key;
            } else if (lane == 0) {
                for (int i = beg + 1; i < end; i++) {
                    int key = g_elist[i];
                    int j = i - 1;
                    while (j >= beg && g_elist[j] > key) { g_elist[j + 1] = g_elist[j]; j--; }
                    g_elist[j + 1] = key;
                }
            }
            __syncwarp();
        }
    }

    const float4* z4 = reinterpret_cast<const float4*>(g_z);
    float4 zd0 = z4[(size_t)n * 16 + cl * 2];
    float4 zd1 = z4[(size_t)n * 16 + cl * 2 + 1];
    float4 at0 = reinterpret_cast<const float4*>(att_l)[cl * 2];
    float4 at1 = reinterpret_cast<const float4*>(att_l)[cl * 2 + 1];

    float m = -1e30f, den = 0.f;
    float4 acc0 = {0, 0, 0, 0}, acc1 = {0, 0, 0, 0};

    for (int cs = beg; cs < end; cs += 32) {
        int p32 = cs + lane;
        int s = n;
        if (p32 < end) {
            int e = g_elist[p32];
            s = (e < EE) ? src[e] : (e - EE);
        }
        int nchunk = min(8, (end - cs + 3) >> 2);
        int sv = __shfl_sync(FULL, s, g);
        float4 zs0 = z4[(size_t)sv * 16 + cl * 2];
        float4 zs1 = z4[(size_t)sv * 16 + cl * 2 + 1];
        for (int it = 0; it < nchunk; it++) {
            int pidx = cs + it * 4 + g;
            bool valid = pidx < end;
            float4 nz0 = zs0, nz1 = zs1;
            if (it + 1 < nchunk) {
                int sv2 = __shfl_sync(FULL, s, (it + 1) * 4 + g);
                nz0 = z4[(size_t)sv2 * 16 + cl * 2];
                nz1 = z4[(size_t)sv2 * 16 + cl * 2 + 1];
            }
            float part =
                lrelu(zs0.x + zd0.x, 0.2f) * at0.x + lrelu(zs0.y + zd0.y, 0.2f) * at0.y +
                lrelu(zs0.z + zd0.z, 0.2f) * at0.z + lrelu(zs0.w + zd0.w, 0.2f) * at0.w +
                lrelu(zs1.x + zd1.x, 0.2f) * at1.x + lrelu(zs1.y + zd1.y, 0.2f) * at1.y +
                lrelu(zs1.z + zd1.z, 0.2f) * at1.z + lrelu(zs1.w + zd1.w, 0.2f) * at1.w;
            part += __shfl_xor_sync(FULL, part, 4);
            part += __shfl_xor_sync(FULL, part, 2);
            part += __shfl_xor_sync(FULL, part, 1);
            float score = valid ? part : -1e30f;
            if (valid && cl == 0) g_score[pidx] = score;
            float nm = fmaxf(m, score);
            float sc = __expf(m - nm);
            float w = __expf(score - nm);
            den = den * sc + w;
            acc0.x = acc0.x * sc + w * zs0.x; acc0.y = acc0.y * sc + w * zs0.y;
            acc0.z = acc0.z * sc + w * zs0.z; acc0.w = acc0.w * sc + w * zs0.w;
            acc1.x = acc1.x * sc + w * zs1.x; acc1.y = acc1.y * sc + w * zs1.y;
            acc1.z = acc1.z * sc + w * zs1.z; acc1.w = acc1.w * sc + w * zs1.w;
            m = nm;
            zs0 = nz0; zs1 = nz1;
        }
    }

    float M = fmaxf(m, __shfl_xor_sync(FULL, m, 8));
    M = fmaxf(M, __shfl_xor_sync(FULL, M, 16));
    float f = __expf(m - M);
    den *= f;
    acc0.x *= f; acc0.y *= f; acc0.z *= f; acc0.w *= f;
    acc1.x *= f; acc1.y *= f; acc1.z *= f; acc1.w *= f;
    den += __shfl_xor_sync(FULL, den, 8);
    den += __shfl_xor_sync(FULL, den, 16);
#pragma unroll
    for (int off = 8; off <= 16; off <<= 1) {
        acc0.x += __shfl_xor_sync(FULL, acc0.x, off);
        acc0.y += __shfl_xor_sync(FULL, acc0.y, off);
        acc0.z += __shfl_xor_sync(FULL, acc0.z, off);
        acc0.w += __shfl_xor_sync(FULL, acc0.w, off);
        acc1.x += __shfl_xor_sync(FULL, acc1.x, off);
        acc1.y += __shfl_xor_sync(FULL, acc1.y, off);
        acc1.z += __shfl_xor_sync(FULL, acc1.z, off);
        acc1.w += __shfl_xor_sync(FULL, acc1.w, off);
    }
    float invd = 1.f / (den + 1e-16f);
    if (g == 0) {
        float4 cb0 = reinterpret_cast<const float4*>(cb_l)[cl * 2];
        float4 cb1 = reinterpret_cast<const float4*>(cb_l)[cl * 2 + 1];
        float4 o0, o1;
        o0.x = acc0.x * invd + cb0.x; o0.y = acc0.y * invd + cb0.y;
        o0.z = acc0.z * invd + cb0.z; o0.w = acc0.w * invd + cb0.w;
        o1.x = acc1.x * invd + cb1.x; o1.y = acc1.y * invd + cb1.y;
        o1.z = acc1.z * invd + cb1.z; o1.w = acc1.w * invd + cb1.w;
        float4* hr = reinterpret_cast<float4*>(g_hraw);
        hr[(size_t)n * 16 + cl * 2] = o0;
        hr[(size_t)n * 16 + cl * 2 + 1] = o1;
    }
    __syncwarp();
    for (int p = beg + lane; p < end; p += 32) {
        alpha_out[g_elist[p]] = __expf(g_score[p] - M) * invd;
    }
}

// ---------------- GEMM MODE2 standalone --------------------------------------
__global__ void __launch_bounds__(GBT, 4) k_gemm2(int layer,
                       const float* __restrict__ bext,
                       const float* __restrict__ gn_w_l,
                       const float* __restrict__ gn_b_l,
                       const float* __restrict__ gn_ms_l) {
    gemm_body<CC, 2>(blockIdx.x, nullptr, layer, bext, gn_w_l, gn_b_l, gn_ms_l);
}

// ---------------- fused GraphNorm stats --------------------------------------
__global__ void k_redF() {
    int t = threadIdx.x;
    int gid = blockIdx.x * blockDim.x + t;
    const int stride = RBLK * 256;
    float a1[4] = {0, 0, 0, 0}, a2[4] = {0, 0, 0, 0};
    const float4* hr = (const float4*)g_hraw;
    for (int i = gid; i < NN * CC / 4; i += stride) {
        float4 v = hr[i];
        a1[0] += v.x; a2[0] += v.x * v.x;
        a1[1] += v.y; a2[1] += v.y * v.y;
        a1[2] += v.z; a2[2] += v.z * v.z;
        a1[3] += v.w; a2[3] += v.w * v.w;
    }
    __shared__ float sh[256 * 8];
#pragma unroll
    for (int q = 0; q < 4; q++) { sh[t * 8 + q] = a1[q]; sh[t * 8 + 4 + q] = a2[q]; }
    __syncthreads();
    if (t < 16) {
        int c0 = (4 * gid) & 63;
        float r1[4] = {0, 0, 0, 0}, r2[4] = {0, 0, 0, 0};
        for (int j = t; j < 256; j += 16) {
#pragma unroll
            for (int q = 0; q < 4; q++) {
                r1[q] += sh[j * 8 + q];
                r2[q] += sh[j * 8 + 4 + q];
            }
        }
#pragma unroll
        for (int q = 0; q < 4; q++) {
            g_part[blockIdx.x * 128 + c0 + q] = r1[q];
            g_part[blockIdx.x * 128 + 64 + c0 + q] = r2[q];
        }
    }
    __threadfence();
    __shared__ int s_last;
    __shared__ float s_half[2][128];
    if (t == 0) s_last = (atomicAdd(&g_rc, 1) == RBLK - 1) ? 1 : 0;
    __syncthreads();
    if (s_last) {
        int ch = t & 127;
        int b0 = (t < 128) ? 0 : RBLK / 2;
        float s0 = 0.f, s1 = 0.f, s2 = 0.f, s3 = 0.f;
        for (int b = b0; b < b0 + RBLK / 2; b += 4) {
            s0 += g_part[(b + 0) * 128 + ch];
            s1 += g_part[(b + 1) * 128 + ch];
            s2 += g_part[(b + 2) * 128 + ch];
            s3 += g_part[(b + 3) * 128 + ch];
        }
        s_half[t >> 7][ch] = (s0 + s1) + (s2 + s3);
        __syncthreads();
        if (t < 128) g_stat[t] = s_half[0][t] + s_half[1][t];
        __syncthreads();
        if (t == 0) g_rc = 0;
    }
}

__global__ void k_norm_last(const float* __restrict__ gn_w_l,
                            const float* __restrict__ gn_b_l,
                            const float* __restrict__ gn_ms_l,
                            float* __restrict__ out) {
    __shared__ float s_sub[CC], s_w[CC], s_b[CC];
    int t = threadIdx.x;
    if (t < CC) {
        double mu = (double)g_stat[t] / (double)NN;
        double g = (double)gn_ms_l[t];
        double var = (double)g_stat[64 + t] / (double)NN - (2.0 * g - g * g) * mu * mu;
        float rstd = (float)(1.0 / sqrt(var + 1e-5));
        s_sub[t] = (float)(g * mu);
        s_w[t] = gn_w_l[t] * rstd;
        s_b[t] = gn_b_l[t];
    }
    __syncthreads();
    int gid = blockIdx.x * blockDim.x + t;
    const int stride = 2048 * 256;
    const float4* hr = (const float4*)g_hraw;
    float4* o0 = (float4*)out;
    float4* o1 = (float4*)(out + NN * CC);
    for (int i = gid; i < NN * CC / 4; i += stride) {
        int c = (4 * i) & 63;
        float4 v = hr[i];
        v.x = lrelu((v.x - s_sub[c + 0]) * s_w[c + 0] + s_b[c + 0], 0.01f);
        v.y = lrelu((v.y - s_sub[c + 1]) * s_w[c + 1] + s_b[c + 1], 0.01f);
        v.z = lrelu((v.z - s_sub[c + 2]) * s_w[c + 2] + s_b[c + 2], 0.01f);
        v.w = lrelu((v.w - s_sub[c + 3]) * s_w[c + 3] + s_b[c + 3], 0.01f);
        o0[i] = v;
        o1[i] = v;
    }
}

extern "C" void kernel_launch(void* const* d_in, const int* in_sizes, int n_in,
                              void* d_out, int out_size) {
    (void)in_sizes; (void)n_in; (void)out_size;
    const float* x       = (const float*)d_in[0];
    const int*   src     = (const int*)d_in[1];
    const int*   dst     = (const int*)d_in[2];
    const float* bn_w    = (const float*)d_in[3];
    const float* bn_b    = (const float*)d_in[4];
    const float* bn_mean = (const float*)d_in[5];
    const float* bn_var  = (const float*)d_in[6];
    const float* in_W    = (const float*)d_in[7];
    const float* in_b    = (const float*)d_in[8];
    const float* lin_W   = (const float*)d_in[9];
    const float* lin_b   = (const float*)d_in[10];
    const float* att     = (const float*)d_in[11];
    const float* conv_b  = (const float*)d_in[12];
    const float* gn_w    = (const float*)d_in[13];
    const float* gn_b    = (const float*)d_in[14];
    const float* gn_ms   = (const float*)d_in[15];
    float* out = (float*)d_out;

    static bool attr_done = false;
    if (!attr_done) {
        cudaFuncSetAttribute(k_fat1, cudaFuncAttributeMaxDynamicSharedMemorySize, GEMM_SMEM);
        cudaFuncSetAttribute(k_fat2, cudaFuncAttributeMaxDynamicSharedMemorySize, GEMM_SMEM);
        cudaFuncSetAttribute(k_gemm2, cudaFuncAttributeMaxDynamicSharedMemorySize, GEMM_SMEM);
        attr_done = true;
    }

    const int HIST_B = (EP + GBT - 1) / GBT;

    k_setup<<<4, 128>>>(bn_w, bn_b, bn_mean, bn_var, in_W, in_b, lin_W);        // 0
    k_fat1<<<GB + HIST_B, GBT, GEMM_SMEM>>>(x, dst);                            // 1
    k_fat2<<<GB + NB1, GBT, GEMM_SMEM>>>(lin_b);                                // 2
    k_scan3<<<NB1, 128>>>();                                                    // 3
    k_scatter<<<(EP + 255) / 256, 256>>>(dst);                                  // 4

    for (int l = 0; l < LL; l++) {
        if (l > 0) {
            k_gemm2<<<GB, GBT, GEMM_SMEM>>>(l, lin_b + l * CC,
                                            gn_w + (l - 1) * CC, gn_b + (l - 1) * CC,
                                            gn_ms + (l - 1) * CC);
        }
        if (l == 0)
            k_edge<true><<<(NN * 32 + 255) / 256, 256>>>(src, att, conv_b,
                                                         out + 2 * NN * CC);
        else
            k_edge<false><<<(NN * 32 + 255) / 256, 256>>>(src, att + l * CC, conv_b + l * CC,
                                                          out + 2 * NN * CC + l * EP);
        k_redF<<<RBLK, 256>>>();
    }
    k_norm_last<<<2048, 256>>>(gn_w + 3 * CC, gn_b + 3 * CC, gn_ms + 3 * CC, out);
}

// round 15
// speedup vs baseline: 1.0367x; 1.0258x over previous
#include <cuda_runtime.h>
#include <math.h>

#define NN 100000
#define EE 1000000
#define EP (EE + NN)
#define FF 128
#define CC 64
#define LL 4
#define NB1 98
#define RBLK 256
#define GBT 128
#define NT 128
#define SXS 68
#define GEMM_SMEM ((NT * SXS + 64 * 64) * 4)
#define GB ((NN + NT - 1) / NT)

__device__ float  g_h[NN * CC];
__device__ float  g_z[NN * CC];
__device__ float  g_hraw[NN * CC];
__device__ float  g_score[EP];
__device__ int    g_cnt[NN];
__device__ int    g_offs[NN + 1];
__device__ int    g_cur[NN];
__device__ int    g_elist[EP];
__device__ int    g_bsum[NB1 + 2];
__device__ float  g_part[RBLK * 128];
__device__ float  g_stat[128];
__device__ float  g_WTin[FF * CC];
__device__ float  g_WT[LL * CC * CC];
__device__ float  g_bp[CC];
__device__ int    g_rc = 0;

__device__ __forceinline__ float lrelu(float v, float s) { return v >= 0.f ? v : s * v; }

__device__ __forceinline__ void ffma2(unsigned long long &d, unsigned long long a,
                                      unsigned long long b) {
    asm("fma.rn.f32x2 %0, %1, %2, %0;" : "+l"(d) : "l"(a), "l"(b));
}
__device__ __forceinline__ unsigned long long pack2(float x) {
    unsigned long long r;
    unsigned int xi = __float_as_uint(x);
    asm("mov.b64 %0, {%1, %1};" : "=l"(r) : "r"(xi));
    return r;
}
__device__ __forceinline__ void unpack2(unsigned long long v, float &lo, float &hi) {
    unsigned int a, b;
    asm("mov.b64 {%0, %1}, %2;" : "=r"(a), "=r"(b) : "l"(v));
    lo = __uint_as_float(a); hi = __uint_as_float(b);
}

// ---------------- setup (weights + zero g_cnt) --------------------------------
__global__ void k_setup(const float* __restrict__ bn_w, const float* __restrict__ bn_b,
                        const float* __restrict__ bn_mean, const float* __restrict__ bn_var,
                        const float* __restrict__ in_W, const float* __restrict__ in_b,
                        const float* __restrict__ lin_W) {
    int b = blockIdx.x;
    int t = threadIdx.x;
    if (b >= 4) {
        int idx = (b - 4) * 128 + t;
        if (idx < NN) g_cnt[idx] = 0;
        return;
    }
    __shared__ float ss[FF], st[FF];
    if (t < FF) {
        float sv = bn_w[t] * rsqrtf(bn_var[t] + 1e-5f);
        ss[t] = sv;
        st[t] = bn_b[t] - bn_mean[t] * sv;
    }
    __syncthreads();
    for (int idx = t; idx < 32 * CC; idx += blockDim.x) {
        int k = b * 32 + idx / CC, c = idx % CC;
        g_WTin[k * CC + c] = in_W[c * FF + k] * ss[k];
    }
    for (int idx = t; idx < CC * CC; idx += blockDim.x) {
        int k = idx / CC, c = idx % CC;
        g_WT[(b * CC + k) * CC + c] = lin_W[(b * CC + c) * CC + k];
    }
    if (b == 0 && t < CC) {
        float acc = in_b[t];
        for (int k = 0; k < FF; k++) acc += in_W[t * FF + k] * st[k];
        g_bp[t] = acc;
    }
}

// ---------------- GEMM body (R12-proven: 128 thr, x-prefetch schedule) -------
template <int K, int MODE>
__device__ __forceinline__ void gemm_body(int bid,
                       const float* __restrict__ ext_in,
                       int layer,
                       const float* __restrict__ bext,
                       const float* __restrict__ gn_w_l,
                       const float* __restrict__ gn_b_l,
                       const float* __restrict__ gn_ms_l) {
    extern __shared__ float smem[];
    float* sX = smem;
    float* sW = smem + NT * SXS;
    __shared__ float sb[CC], s_sub[CC], s_scl[CC], s_off[CC];
    int t = threadIdx.x;
    if (t < CC) sb[t] = (MODE == 0) ? g_bp[t] : bext[t];
    if (MODE == 2 && t < CC) {
        double mu = (double)g_stat[t] / (double)NN;
        double g = (double)gn_ms_l[t];
        double var = (double)g_stat[64 + t] / (double)NN - (2.0 * g - g * g) * mu * mu;
        float rstd = (float)(1.0 / sqrt(var + 1e-5));
        s_sub[t] = (float)(g * mu);
        s_scl[t] = gn_w_l[t] * rstd;
        s_off[t] = gn_b_l[t];
    }
    __syncthreads();

    const float* xin = (MODE == 0) ? ext_in : (MODE == 1 ? (const float*)g_h
                                                         : (const float*)g_hraw);
    const float* WT = (MODE == 0) ? (const float*)g_WTin
                                  : (const float*)(g_WT + layer * CC * CC);
    int base = bid * NT;
    int tx = t & 7, ty = t >> 3;

    unsigned long long acc[8][4];
#pragma unroll
    for (int i = 0; i < 8; i++)
#pragma unroll
        for (int j = 0; j < 4; j++) acc[i][j] = 0ull;

    const int NCHUNK = K / 64;
    for (int kc = 0; kc < NCHUNK; kc++) {
#pragma unroll
        for (int j = 0; j < 16; j++) {
            int idx = t + j * GBT;
            int node = idx >> 4, kq = idx & 15;
            int gn = base + node;
            float4 v = make_float4(0.f, 0.f, 0.f, 0.f);
            if (gn < NN)
                v = *(const float4*)(xin + (size_t)gn * K + kc * 64 + kq * 4);
            if (MODE == 2) {
                int c = kq * 4;
                v.x = lrelu((v.x - s_sub[c + 0]) * s_scl[c + 0] + s_off[c + 0], 0.01f);
                v.y = lrelu((v.y - s_sub[c + 1]) * s_scl[c + 1] + s_off[c + 1], 0.01f);
                v.z = lrelu((v.z - s_sub[c + 2]) * s_scl[c + 2] + s_off[c + 2], 0.01f);
                v.w = lrelu((v.w - s_sub[c + 3]) * s_scl[c + 3] + s_off[c + 3], 0.01f);
            }
            *(float4*)&sX[node * SXS + kq * 4] = v;
        }
#pragma unroll
        for (int j = 0; j < 8; j++) {
            int idx = t + j * GBT;
            ((float4*)sW)[idx] = ((const float4*)(WT + kc * 64 * CC))[idx];
        }
        __syncthreads();

        float2 xv[8];
#pragma unroll
        for (int i = 0; i < 8; i++)
            xv[i] = *(const float2*)&sX[(ty + i * 16) * SXS + 0];

        for (int kq = 0; kq < 64; kq += 2) {
            ulonglong2 wa0 = *(const ulonglong2*)&sW[kq * 64 + tx * 8];
            ulonglong2 wb0 = *(const ulonglong2*)&sW[kq * 64 + tx * 8 + 4];
            ulonglong2 wa1 = *(const ulonglong2*)&sW[(kq + 1) * 64 + tx * 8];
            ulonglong2 wb1 = *(const ulonglong2*)&sW[(kq + 1) * 64 + tx * 8 + 4];
            float2 xn[8];
            if (kq + 2 < 64) {
#pragma unroll
                for (int i = 0; i < 8; i++)
                    xn[i] = *(const float2*)&sX[(ty + i * 16) * SXS + kq + 2];
            }
#pragma unroll
            for (int i = 0; i < 8; i++) {
                unsigned long long xp = pack2(xv[i].x);
                ffma2(acc[i][0], xp, wa0.x);
                ffma2(acc[i][1], xp, wa0.y);
                ffma2(acc[i][2], xp, wb0.x);
                ffma2(acc[i][3], xp, wb0.y);
            }
#pragma unroll
            for (int i = 0; i < 8; i++) {
                unsigned long long xp = pack2(xv[i].y);
                ffma2(acc[i][0], xp, wa1.x);
                ffma2(acc[i][1], xp, wa1.y);
                ffma2(acc[i][2], xp, wb1.x);
                ffma2(acc[i][3], xp, wb1.y);
            }
            if (kq + 2 < 64) {
#pragma unroll
                for (int i = 0; i < 8; i++) xv[i] = xn[i];
            }
        }
        if (kc + 1 < NCHUNK) __syncthreads();
    }

    float4 b0 = *(const float4*)&sb[tx * 8];
    float4 b1 = *(const float4*)&sb[tx * 8 + 4];
    float* outp = (MODE == 0) ? g_h : g_z;
#pragma unroll
    for (int i = 0; i < 8; i++) {
        int node = base + ty + i * 16;
        if (node >= NN) continue;
        float4 r0, r1;
        unpack2(acc[i][0], r0.x, r0.y);
        unpack2(acc[i][1], r0.z, r0.w);
        unpack2(acc[i][2], r1.x, r1.y);
        unpack2(acc[i][3], r1.z, r1.w);
        r0.x += b0.x; r0.y += b0.y; r0.z += b0.z; r0.w += b0.w;
        r1.x += b1.x; r1.y += b1.y; r1.z += b1.z; r1.w += b1.w;
        if (MODE == 0) {
            r0.x = lrelu(r0.x, 0.01f); r0.y = lrelu(r0.y, 0.01f);
            r0.z = lrelu(r0.z, 0.01f); r0.w = lrelu(r0.w, 0.01f);
            r1.x = lrelu(r1.x, 0.01f); r1.y = lrelu(r1.y, 0.01f);
            r1.z = lrelu(r1.z, 0.01f); r1.w = lrelu(r1.w, 0.01f);
        }
        float* op = outp + (size_t)node * CC + tx * 8;
        *(float4*)op = r0;
        *(float4*)(op + 4) = r1;
    }
}

// ---------------- fat kernels ------------------------------------------------
__global__ void __launch_bounds__(GBT, 4) k_fat1(const float* __restrict__ x,
                                                 const int* __restrict__ dst) {
    if (blockIdx.x < GB) {
        gemm_body<FF, 0>(blockIdx.x, x, 0, nullptr, nullptr, nullptr, nullptr);
    } else {
        int i = (blockIdx.x - GB) * GBT + threadIdx.x;
        if (i < EP) {
            int d = i < EE ? dst[i] : i - EE;
            atomicAdd(&g_cnt[d], 1);
        }
    }
}

__global__ void __launch_bounds__(GBT, 4) k_fat2(const float* __restrict__ lin_b) {
    if (blockIdx.x < GB) {
        gemm_body<CC, 1>(blockIdx.x, nullptr, 0, lin_b, nullptr, nullptr, nullptr);
        return;
    }
    int b = blockIdx.x - GB;
    int t = threadIdx.x;
    int base = b * 1024;
    int loc[8];
    int run = 0;
#pragma unroll
    for (int j = 0; j < 8; j++) {
        int i = base + t * 8 + j;
        int v = (i < NN) ? g_cnt[i] : 0;
        run += v;
        loc[j] = run;
    }
    __shared__ int sT[128];
    sT[t] = run;
    __syncthreads();
    for (int off = 1; off < 128; off <<= 1) {
        int add = (t >= off) ? sT[t - off] : 0;
        __syncthreads();
        sT[t] += add;
        __syncthreads();
    }
    int excl = sT[t] - run;
#pragma unroll
    for (int j = 0; j < 8; j++) {
        int i = base + t * 8 + j;
        if (i < NN) g_cur[i] = excl + loc[j];
    }
    if (t == 127) g_bsum[b] = sT[127];
}

__global__ void k_scan3() {
    __shared__ int sv[128];
    __shared__ int sOff;
    int t = threadIdx.x;
    int b = blockIdx.x;
    sv[t] = (t < b) ? g_bsum[t] : 0;
    __syncthreads();
    for (int off = 64; off >= 1; off >>= 1) {
        if (t < off) sv[t] += sv[t + off];
        __syncthreads();
    }
    if (t == 0) sOff = sv[0];
    __syncthreads();
    int boff = sOff;
    int base = b * 1024;
#pragma unroll
    for (int j = 0; j < 8; j++) {
        int i = base + t * 8 + j;
        if (i < NN) {
            int incl = g_cur[i];
            int ex = incl - g_cnt[i] + boff;
            g_offs[i] = ex;
            g_cur[i] = ex;
            if (i == NN - 1) g_offs[NN] = incl + boff;
        }
    }
}

__global__ void k_scatter(const int* __restrict__ dst) {
    int i = blockIdx.x * blockDim.x + threadIdx.x;
    if (i >= EP) return;
    int d = i < EE ? dst[i] : i - EE;
    int pos = atomicAdd(&g_cur[d], 1);
    g_elist[pos] = i;
}

// ---------------- edge pass (fused segment sort on layer 0) ------------------
template <bool SORT>
__global__ void k_edge(const int* __restrict__ src,
                       const float* __restrict__ att_l,
                       const float* __restrict__ cb_l,
                       float* __restrict__ alpha_out) {
    const unsigned FULL = 0xffffffffu;
    int warp = (blockIdx.x * blockDim.x + threadIdx.x) >> 5;
    int lane = threadIdx.x & 31;
    if (warp >= NN) return;
    int n = warp;
    int g = lane >> 3, cl = lane & 7;

    int beg = g_offs[n], end = g_offs[n + 1];

    if (SORT) {
        int d = end - beg;
        if (d > 1) {
            if (d <= 32) {
                int key = (beg + lane < end) ? g_elist[beg + lane] : 0x7fffffff;
#pragma unroll
                for (int ph = 0; ph < 32; ph++) {
                    int odd = ph & 1;
                    bool lo = (((lane ^ odd) & 1) == 0);
                    int partner = lo ? lane + 1 : lane - 1;
                    int pv = __shfl_sync(FULL, key, partner & 31);
                    if (partner >= 0 && partner < 32)
                        key = lo ? min(key, pv) : max(key, pv);
                }
                if (lane < d) g_elist[beg + lane] = key;
            } else if (lane == 0) {
                for (int i = beg + 1; i < end; i++) {
                    int key = g_elist[i];
                    int j = i - 1;
                    while (j >= beg && g_elist[j] > key) { g_elist[j + 1] = g_elist[j]; j--; }
                    g_elist[j + 1] = key;
                }
            }
            __syncwarp();
        }
    }

    const float4* z4 = reinterpret_cast<const float4*>(g_z);
    float4 zd0 = z4[(size_t)n * 16 + cl * 2];
    float4 zd1 = z4[(size_t)n * 16 + cl * 2 + 1];
    float4 at0 = reinterpret_cast<const float4*>(att_l)[cl * 2];
    float4 at1 = reinterpret_cast<const float4*>(att_l)[cl * 2 + 1];

    float m = -1e30f, den = 0.f;
    float4 acc0 = {0, 0, 0, 0}, acc1 = {0, 0, 0, 0};

    for (int cs = beg; cs < end; cs += 32) {
        int p32 = cs + lane;
        int s = n;
        if (p32 < end) {
            int e = g_elist[p32];
            s = (e < EE) ? src[e] : (e - EE);
        }
        int nchunk = min(8, (end - cs + 3) >> 2);
        int sv = __shfl_sync(FULL, s, g);
        float4 zs0 = z4[(size_t)sv * 16 + cl * 2];
        float4 zs1 = z4[(size_t)sv * 16 + cl * 2 + 1];
        for (int it = 0; it < nchunk; it++) {
            int pidx = cs + it * 4 + g;
            bool valid = pidx < end;
            float4 nz0 = zs0, nz1 = zs1;
            if (it + 1 < nchunk) {
                int sv2 = __shfl_sync(FULL, s, (it + 1) * 4 + g);
                nz0 = z4[(size_t)sv2 * 16 + cl * 2];
                nz1 = z4[(size_t)sv2 * 16 + cl * 2 + 1];
            }
            float part =
                lrelu(zs0.x + zd0.x, 0.2f) * at0.x + lrelu(zs0.y + zd0.y, 0.2f) * at0.y +
                lrelu(zs0.z + zd0.z, 0.2f) * at0.z + lrelu(zs0.w + zd0.w, 0.2f) * at0.w +
                lrelu(zs1.x + zd1.x, 0.2f) * at1.x + lrelu(zs1.y + zd1.y, 0.2f) * at1.y +
                lrelu(zs1.z + zd1.z, 0.2f) * at1.z + lrelu(zs1.w + zd1.w, 0.2f) * at1.w;
            part += __shfl_xor_sync(FULL, part, 4);
            part += __shfl_xor_sync(FULL, part, 2);
            part += __shfl_xor_sync(FULL, part, 1);
            float score = valid ? part : -1e30f;
            if (valid && cl == 0) g_score[pidx] = score;
            float nm = fmaxf(m, score);
            float sc = __expf(m - nm);
            float w = __expf(score - nm);
            den = den * sc + w;
            acc0.x = acc0.x * sc + w * zs0.x; acc0.y = acc0.y * sc + w * zs0.y;
            acc0.z = acc0.z * sc + w * zs0.z; acc0.w = acc0.w * sc + w * zs0.w;
            acc1.x = acc1.x * sc + w * zs1.x; acc1.y = acc1.y * sc + w * zs1.y;
            acc1.z = acc1.z * sc + w * zs1.z; acc1.w = acc1.w * sc + w * zs1.w;
            m = nm;
            zs0 = nz0; zs1 = nz1;
        }
    }

    float M = fmaxf(m, __shfl_xor_sync(FULL, m, 8));
    M = fmaxf(M, __shfl_xor_sync(FULL, M, 16));
    float f = __expf(m - M);
    den *= f;
    acc0.x *= f; acc0.y *= f; acc0.z *= f; acc0.w *= f;
    acc1.x *= f; acc1.y *= f; acc1.z *= f; acc1.w *= f;
    den += __shfl_xor_sync(FULL, den, 8);
    den += __shfl_xor_sync(FULL, den, 16);
#pragma unroll
    for (int off = 8; off <= 16; off <<= 1) {
        acc0.x += __shfl_xor_sync(FULL, acc0.x, off);
        acc0.y += __shfl_xor_sync(FULL, acc0.y, off);
        acc0.z += __shfl_xor_sync(FULL, acc0.z, off);
        acc0.w += __shfl_xor_sync(FULL, acc0.w, off);
        acc1.x += __shfl_xor_sync(FULL, acc1.x, off);
        acc1.y += __shfl_xor_sync(FULL, acc1.y, off);
        acc1.z += __shfl_xor_sync(FULL, acc1.z, off);
        acc1.w += __shfl_xor_sync(FULL, acc1.w, off);
    }
    float invd = 1.f / (den + 1e-16f);
    if (g == 0) {
        float4 cb0 = reinterpret_cast<const float4*>(cb_l)[cl * 2];
        float4 cb1 = reinterpret_cast<const float4*>(cb_l)[cl * 2 + 1];
        float4 o0, o1;
        o0.x = acc0.x * invd + cb0.x; o0.y = acc0.y * invd + cb0.y;
        o0.z = acc0.z * invd + cb0.z; o0.w = acc0.w * invd + cb0.w;
        o1.x = acc1.x * invd + cb1.x; o1.y = acc1.y * invd + cb1.y;
        o1.z = acc1.z * invd + cb1.z; o1.w = acc1.w * invd + cb1.w;
        float4* hr = reinterpret_cast<float4*>(g_hraw);
        hr[(size_t)n * 16 + cl * 2] = o0;
        hr[(size_t)n * 16 + cl * 2 + 1] = o1;
    }
    __syncwarp();
    for (int p = beg + lane; p < end; p += 32) {
        alpha_out[g_elist[p]] = __expf(g_score[p] - M) * invd;
    }
}

// ---------------- GEMM MODE2 standalone --------------------------------------
__global__ void __launch_bounds__(GBT, 4) k_gemm2(int layer,
                       const float* __restrict__ bext,
                       const float* __restrict__ gn_w_l,
                       const float* __restrict__ gn_b_l,
                       const float* __restrict__ gn_ms_l) {
    gemm_body<CC, 2>(blockIdx.x, nullptr, layer, bext, gn_w_l, gn_b_l, gn_ms_l);
}

// ---------------- fused GraphNorm stats (RBLK=256) ---------------------------
__global__ void k_redF() {
    int t = threadIdx.x;
    int gid = blockIdx.x * blockDim.x + t;
    const int stride = RBLK * 256;
    float a1[4] = {0, 0, 0, 0}, a2[4] = {0, 0, 0, 0};
    const float4* hr = (const float4*)g_hraw;
    for (int i = gid; i < NN * CC / 4; i += stride) {
        float4 v = hr[i];
        a1[0] += v.x; a2[0] += v.x * v.x;
        a1[1] += v.y; a2[1] += v.y * v.y;
        a1[2] += v.z; a2[2] += v.z * v.z;
        a1[3] += v.w; a2[3] += v.w * v.w;
    }
    __shared__ float sh[256 * 8];
#pragma unroll
    for (int q = 0; q < 4; q++) { sh[t * 8 + q] = a1[q]; sh[t * 8 + 4 + q] = a2[q]; }
    __syncthreads();
    if (t < 16) {
        int c0 = (4 * gid) & 63;
        float r1[4] = {0, 0, 0, 0}, r2[4] = {0, 0, 0, 0};
        for (int j = t; j < 256; j += 16) {
#pragma unroll
            for (int q = 0; q < 4; q++) {
                r1[q] += sh[j * 8 + q];
                r2[q] += sh[j * 8 + 4 + q];
            }
        }
#pragma unroll
        for (int q = 0; q < 4; q++) {
            g_part[blockIdx.x * 128 + c0 + q] = r1[q];
            g_part[blockIdx.x * 128 + 64 + c0 + q] = r2[q];
        }
    }
    __threadfence();
    __shared__ int s_last;
    __shared__ float s_half[2][128];
    if (t == 0) s_last = (atomicAdd(&g_rc, 1) == RBLK - 1) ? 1 : 0;
    __syncthreads();
    if (s_last) {
        int ch = t & 127;
        int b0 = (t < 128) ? 0 : RBLK / 2;
        float s0 = 0.f, s1 = 0.f, s2 = 0.f, s3 = 0.f;
        for (int b = b0; b < b0 + RBLK / 2; b += 4) {
            s0 += g_part[(b + 0) * 128 + ch];
            s1 += g_part[(b + 1) * 128 + ch];
            s2 += g_part[(b + 2) * 128 + ch];
            s3 += g_part[(b + 3) * 128 + ch];
        }
        s_half[t >> 7][ch] = (s0 + s1) + (s2 + s3);
        __syncthreads();
        if (t < 128) g_stat[t] = s_half[0][t] + s_half[1][t];
        __syncthreads();
        if (t == 0) g_rc = 0;
    }
}

__global__ void k_norm_last(const float* __restrict__ gn_w_l,
                            const float* __restrict__ gn_b_l,
                            const float* __restrict__ gn_ms_l,
                            float* __restrict__ out) {
    __shared__ float s_sub[CC], s_w[CC], s_b[CC];
    int t = threadIdx.x;
    if (t < CC) {
        double mu = (double)g_stat[t] / (double)NN;
        double g = (double)gn_ms_l[t];
        double var = (double)g_stat[64 + t] / (double)NN - (2.0 * g - g * g) * mu * mu;
        float rstd = (float)(1.0 / sqrt(var + 1e-5));
        s_sub[t] = (float)(g * mu);
        s_w[t] = gn_w_l[t] * rstd;
        s_b[t] = gn_b_l[t];
    }
    __syncthreads();
    int gid = blockIdx.x * blockDim.x + t;
    const int stride = 2048 * 256;
    const float4* hr = (const float4*)g_hraw;
    float4* o0 = (float4*)out;
    float4* o1 = (float4*)(out + NN * CC);
    for (int i = gid; i < NN * CC / 4; i += stride) {
        int c = (4 * i) & 63;
        float4 v = hr[i];
        v.x = lrelu((v.x - s_sub[c + 0]) * s_w[c + 0] + s_b[c + 0], 0.01f);
        v.y = lrelu((v.y - s_sub[c + 1]) * s_w[c + 1] + s_b[c + 1], 0.01f);
        v.z = lrelu((v.z - s_sub[c + 2]) * s_w[c + 2] + s_b[c + 2], 0.01f);
        v.w = lrelu((v.w - s_sub[c + 3]) * s_w[c + 3] + s_b[c + 3], 0.01f);
        o0[i] = v;
        o1[i] = v;
    }
}

extern "C" void kernel_launch(void* const* d_in, const int* in_sizes, int n_in,
                              void* d_out, int out_size) {
    (void)in_sizes; (void)n_in; (void)out_size;
    const float* x       = (const float*)d_in[0];
    const int*   src     = (const int*)d_in[1];
    const int*   dst     = (const int*)d_in[2];
    const float* bn_w    = (const float*)d_in[3];
    const float* bn_b    = (const float*)d_in[4];
    const float* bn_mean = (const float*)d_in[5];
    const float* bn_var  = (const float*)d_in[6];
    const float* in_W    = (const float*)d_in[7];
    const float* in_b    = (const float*)d_in[8];
    const float* lin_W   = (const float*)d_in[9];
    const float* lin_b   = (const float*)d_in[10];
    const float* att     = (const float*)d_in[11];
    const float* conv_b  = (const float*)d_in[12];
    const float* gn_w    = (const float*)d_in[13];
    const float* gn_b    = (const float*)d_in[14];
    const float* gn_ms   = (const float*)d_in[15];
    float* out = (float*)d_out;

    static bool attr_done = false;
    if (!attr_done) {
        cudaFuncSetAttribute(k_fat1, cudaFuncAttributeMaxDynamicSharedMemorySize, GEMM_SMEM);
        cudaFuncSetAttribute(k_fat2, cudaFuncAttributeMaxDynamicSharedMemorySize, GEMM_SMEM);
        cudaFuncSetAttribute(k_gemm2, cudaFuncAttributeMaxDynamicSharedMemorySize, GEMM_SMEM);
        attr_done = true;
    }

    const int SETUP_B = 4 + (NN + 127) / 128;
    const int HIST_B = (EP + GBT - 1) / GBT;

    k_setup<<<SETUP_B, 128>>>(bn_w, bn_b, bn_mean, bn_var, in_W, in_b, lin_W);  // 0
    k_fat1<<<GB + HIST_B, GBT, GEMM_SMEM>>>(x, dst);                            // 1
    k_fat2<<<GB + NB1, GBT, GEMM_SMEM>>>(lin_b);                                // 2
    k_scan3<<<NB1, 128>>>();                                                    // 3
    k_scatter<<<(EP + 255) / 256, 256>>>(dst);                                  // 4

    for (int l = 0; l < LL; l++) {
        if (l > 0) {
            k_gemm2<<<GB, GBT, GEMM_SMEM>>>(l, lin_b + l * CC,
                                            gn_w + (l - 1) * CC, gn_b + (l - 1) * CC,
                                            gn_ms + (l - 1) * CC);
        }
        if (l == 0)
            k_edge<true><<<(NN * 32 + 255) / 256, 256>>>(src, att, conv_b,
                                                         out + 2 * NN * CC);
        else
            k_edge<false><<<(NN * 32 + 255) / 256, 256>>>(src, att + l * CC, conv_b + l * CC,
                                                          out + 2 * NN * CC + l * EP);
        k_redF<<<RBLK, 256>>>();
    }
    k_norm_last<<<2048, 256>>>(gn_w + 3 * CC, gn_b + 3 * CC, gn_ms + 3 * CC, out);
}

// round 16
// speedup vs baseline: 1.0414x; 1.0046x over previous
#include <cuda_runtime.h>
#include <math.h>

#define NN 100000
#define EE 1000000
#define EP (EE + NN)
#define FF 128
#define CC 64
#define LL 4
#define NB1 98
#define RBLK 256
#define GBT 128
#define NT 128
#define SXS 68
#define GEMM_SMEM ((NT * SXS + 64 * 64) * 4)
#define GB ((NN + NT - 1) / NT)
#define NORMB 1184

__device__ float  g_h[NN * CC];
__device__ float  g_z[NN * CC];
__device__ float  g_hraw[NN * CC];
__device__ float  g_score[EP];
__device__ int    g_cnt[NN];
__device__ int    g_offs[NN + 1];
__device__ int    g_cur[NN];
__device__ int    g_elist[EP];
__device__ int    g_bsum[NB1 + 2];
__device__ float  g_part[RBLK * 128];
__device__ float  g_stat[128];
__device__ float  g_WTin[FF * CC];
__device__ float  g_WT[LL * CC * CC];
__device__ float  g_bp[CC];
__device__ int    g_rc = 0;

__device__ __forceinline__ float lrelu(float v, float s) { return v >= 0.f ? v : s * v; }

__device__ __forceinline__ void ffma2(unsigned long long &d, unsigned long long a,
                                      unsigned long long b) {
    asm("fma.rn.f32x2 %0, %1, %2, %0;" : "+l"(d) : "l"(a), "l"(b));
}
__device__ __forceinline__ unsigned long long pack2(float x) {
    unsigned long long r;
    unsigned int xi = __float_as_uint(x);
    asm("mov.b64 %0, {%1, %1};" : "=l"(r) : "r"(xi));
    return r;
}
__device__ __forceinline__ void unpack2(unsigned long long v, float &lo, float &hi) {
    unsigned int a, b;
    asm("mov.b64 {%0, %1}, %2;" : "=r"(a), "=r"(b) : "l"(v));
    lo = __uint_as_float(a); hi = __uint_as_float(b);
}

// ---------------- setup (weights + zero g_cnt) --------------------------------
__global__ void k_setup(const float* __restrict__ bn_w, const float* __restrict__ bn_b,
                        const float* __restrict__ bn_mean, const float* __restrict__ bn_var,
                        const float* __restrict__ in_W, const float* __restrict__ in_b,
                        const float* __restrict__ lin_W) {
    int b = blockIdx.x;
    int t = threadIdx.x;
    if (b >= 4) {
        int idx = (b - 4) * 128 + t;
        if (idx < NN) g_cnt[idx] = 0;
        return;
    }
    __shared__ float ss[FF], st[FF];
    if (t < FF) {
        float sv = bn_w[t] * rsqrtf(bn_var[t] + 1e-5f);
        ss[t] = sv;
        st[t] = bn_b[t] - bn_mean[t] * sv;
    }
    __syncthreads();
    for (int idx = t; idx < 32 * CC; idx += blockDim.x) {
        int k = b * 32 + idx / CC, c = idx % CC;
        g_WTin[k * CC + c] = in_W[c * FF + k] * ss[k];
    }
    for (int idx = t; idx < CC * CC; idx += blockDim.x) {
        int k = idx / CC, c = idx % CC;
        g_WT[(b * CC + k) * CC + c] = lin_W[(b * CC + c) * CC + k];
    }
    if (b == 0 && t < CC) {
        float acc = in_b[t];
        for (int k = 0; k < FF; k++) acc += in_W[t * FF + k] * st[k];
        g_bp[t] = acc;
    }
}

// ---------------- GEMM body (R12-proven: 128 thr, x-prefetch schedule) -------
template <int K, int MODE>
__device__ __forceinline__ void gemm_body(int bid,
                       const float* __restrict__ ext_in,
                       int layer,
                       const float* __restrict__ bext,
                       const float* __restrict__ gn_w_l,
                       const float* __restrict__ gn_b_l,
                       const float* __restrict__ gn_ms_l) {
    extern __shared__ float smem[];
    float* sX = smem;
    float* sW = smem + NT * SXS;
    __shared__ float sb[CC], s_sub[CC], s_scl[CC], s_off[CC];
    int t = threadIdx.x;
    if (t < CC) sb[t] = (MODE == 0) ? g_bp[t] : bext[t];
    if (MODE == 2 && t < CC) {
        double mu = (double)g_stat[t] / (double)NN;
        double g = (double)gn_ms_l[t];
        double var = (double)g_stat[64 + t] / (double)NN - (2.0 * g - g * g) * mu * mu;
        float rstd = (float)(1.0 / sqrt(var + 1e-5));
        s_sub[t] = (float)(g * mu);
        s_scl[t] = gn_w_l[t] * rstd;
        s_off[t] = gn_b_l[t];
    }
    __syncthreads();

    const float* xin = (MODE == 0) ? ext_in : (MODE == 1 ? (const float*)g_h
                                                         : (const float*)g_hraw);
    const float* WT = (MODE == 0) ? (const float*)g_WTin
                                  : (const float*)(g_WT + layer * CC * CC);
    int base = bid * NT;
    int tx = t & 7, ty = t >> 3;

    unsigned long long acc[8][4];
#pragma unroll
    for (int i = 0; i < 8; i++)
#pragma unroll
        for (int j = 0; j < 4; j++) acc[i][j] = 0ull;

    const int NCHUNK = K / 64;
    for (int kc = 0; kc < NCHUNK; kc++) {
#pragma unroll
        for (int j = 0; j < 16; j++) {
            int idx = t + j * GBT;
            int node = idx >> 4, kq = idx & 15;
            int gn = base + node;
            float4 v = make_float4(0.f, 0.f, 0.f, 0.f);
            if (gn < NN)
                v = *(const float4*)(xin + (size_t)gn * K + kc * 64 + kq * 4);
            if (MODE == 2) {
                int c = kq * 4;
                v.x = lrelu((v.x - s_sub[c + 0]) * s_scl[c + 0] + s_off[c + 0], 0.01f);
                v.y = lrelu((v.y - s_sub[c + 1]) * s_scl[c + 1] + s_off[c + 1], 0.01f);
                v.z = lrelu((v.z - s_sub[c + 2]) * s_scl[c + 2] + s_off[c + 2], 0.01f);
                v.w = lrelu((v.w - s_sub[c + 3]) * s_scl[c + 3] + s_off[c + 3], 0.01f);
            }
            *(float4*)&sX[node * SXS + kq * 4] = v;
        }
#pragma unroll
        for (int j = 0; j < 8; j++) {
            int idx = t + j * GBT;
            ((float4*)sW)[idx] = ((const float4*)(WT + kc * 64 * CC))[idx];
        }
        __syncthreads();

        float2 xv[8];
#pragma unroll
        for (int i = 0; i < 8; i++)
            xv[i] = *(const float2*)&sX[(ty + i * 16) * SXS + 0];

        for (int kq = 0; kq < 64; kq += 2) {
            ulonglong2 wa0 = *(const ulonglong2*)&sW[kq * 64 + tx * 8];
            ulonglong2 wb0 = *(const ulonglong2*)&sW[kq * 64 + tx * 8 + 4];
            ulonglong2 wa1 = *(const ulonglong2*)&sW[(kq + 1) * 64 + tx * 8];
            ulonglong2 wb1 = *(const ulonglong2*)&sW[(kq + 1) * 64 + tx * 8 + 4];
            float2 xn[8];
            if (kq + 2 < 64) {
#pragma unroll
                for (int i = 0; i < 8; i++)
                    xn[i] = *(const float2*)&sX[(ty + i * 16) * SXS + kq + 2];
            }
#pragma unroll
            for (int i = 0; i < 8; i++) {
                unsigned long long xp = pack2(xv[i].x);
                ffma2(acc[i][0], xp, wa0.x);
                ffma2(acc[i][1], xp, wa0.y);
                ffma2(acc[i][2], xp, wb0.x);
                ffma2(acc[i][3], xp, wb0.y);
            }
#pragma unroll
            for (int i = 0; i < 8; i++) {
                unsigned long long xp = pack2(xv[i].y);
                ffma2(acc[i][0], xp, wa1.x);
                ffma2(acc[i][1], xp, wa1.y);
                ffma2(acc[i][2], xp, wb1.x);
                ffma2(acc[i][3], xp, wb1.y);
            }
            if (kq + 2 < 64) {
#pragma unroll
                for (int i = 0; i < 8; i++) xv[i] = xn[i];
            }
        }
        if (kc + 1 < NCHUNK) __syncthreads();
    }

    float4 b0 = *(const float4*)&sb[tx * 8];
    float4 b1 = *(const float4*)&sb[tx * 8 + 4];
    float* outp = (MODE == 0) ? g_h : g_z;
#pragma unroll
    for (int i = 0; i < 8; i++) {
        int node = base + ty + i * 16;
        if (node >= NN) continue;
        float4 r0, r1;
        unpack2(acc[i][0], r0.x, r0.y);
        unpack2(acc[i][1], r0.z, r0.w);
        unpack2(acc[i][2], r1.x, r1.y);
        unpack2(acc[i][3], r1.z, r1.w);
        r0.x += b0.x; r0.y += b0.y; r0.z += b0.z; r0.w += b0.w;
        r1.x += b1.x; r1.y += b1.y; r1.z += b1.z; r1.w += b1.w;
        if (MODE == 0) {
            r0.x = lrelu(r0.x, 0.01f); r0.y = lrelu(r0.y, 0.01f);
            r0.z = lrelu(r0.z, 0.01f); r0.w = lrelu(r0.w, 0.01f);
            r1.x = lrelu(r1.x, 0.01f); r1.y = lrelu(r1.y, 0.01f);
            r1.z = lrelu(r1.z, 0.01f); r1.w = lrelu(r1.w, 0.01f);
        }
        float* op = outp + (size_t)node * CC + tx * 8;
        *(float4*)op = r0;
        *(float4*)(op + 4) = r1;
    }
}

// ---------------- fat kernels ------------------------------------------------
__global__ void __launch_bounds__(GBT, 4) k_fat1(const float* __restrict__ x,
                                                 const int* __restrict__ dst) {
    if (blockIdx.x < GB) {
        gemm_body<FF, 0>(blockIdx.x, x, 0, nullptr, nullptr, nullptr, nullptr);
    } else {
        int i = (blockIdx.x - GB) * GBT + threadIdx.x;
        if (i < EP) {
            int d = i < EE ? dst[i] : i - EE;
            atomicAdd(&g_cnt[d], 1);
        }
    }
}

__global__ void __launch_bounds__(GBT, 4) k_fat2(const float* __restrict__ lin_b) {
    if (blockIdx.x < GB) {
        gemm_body<CC, 1>(blockIdx.x, nullptr, 0, lin_b, nullptr, nullptr, nullptr);
        return;
    }
    int b = blockIdx.x - GB;
    int t = threadIdx.x;
    int base = b * 1024;
    int loc[8];
    int run = 0;
#pragma unroll
    for (int j = 0; j < 8; j++) {
        int i = base + t * 8 + j;
        int v = (i < NN) ? g_cnt[i] : 0;
        run += v;
        loc[j] = run;
    }
    __shared__ int sT[128];
    sT[t] = run;
    __syncthreads();
    for (int off = 1; off < 128; off <<= 1) {
        int add = (t >= off) ? sT[t - off] : 0;
        __syncthreads();
        sT[t] += add;
        __syncthreads();
    }
    int excl = sT[t] - run;
#pragma unroll
    for (int j = 0; j < 8; j++) {
        int i = base + t * 8 + j;
        if (i < NN) g_cur[i] = excl + loc[j];
    }
    if (t == 127) g_bsum[b] = sT[127];
}

__global__ void k_scan3() {
    __shared__ int sv[128];
    __shared__ int sOff;
    int t = threadIdx.x;
    int b = blockIdx.x;
    sv[t] = (t < b) ? g_bsum[t] : 0;
    __syncthreads();
    for (int off = 64; off >= 1; off >>= 1) {
        if (t < off) sv[t] += sv[t + off];
        __syncthreads();
    }
    if (t == 0) sOff = sv[0];
    __syncthreads();
    int boff = sOff;
    int base = b * 1024;
#pragma unroll
    for (int j = 0; j < 8; j++) {
        int i = base + t * 8 + j;
        if (i < NN) {
            int incl = g_cur[i];
            int ex = incl - g_cnt[i] + boff;
            g_offs[i] = ex;
            g_cur[i] = ex;
            if (i == NN - 1) g_offs[NN] = incl + boff;
        }
    }
}

__global__ void k_scatter(const int* __restrict__ dst) {
    int i = blockIdx.x * blockDim.x + threadIdx.x;
    if (i >= EP) return;
    int d = i < EE ? dst[i] : i - EE;
    int pos = atomicAdd(&g_cur[d], 1);
    g_elist[pos] = i;
}

// ---------------- edge pass (fused segment sort on layer 0) ------------------
template <bool SORT>
__global__ void k_edge(const int* __restrict__ src,
                       const float* __restrict__ att_l,
                       const float* __restrict__ cb_l,
                       float* __restrict__ alpha_out) {
    const unsigned FULL = 0xffffffffu;
    int warp = (blockIdx.x * blockDim.x + threadIdx.x) >> 5;
    int lane = threadIdx.x & 31;
    if (warp >= NN) return;
    int n = warp;
    int g = lane >> 3, cl = lane & 7;

    int beg = g_offs[n], end = g_offs[n + 1];

    if (SORT) {
        int d = end - beg;
        if (d > 1) {
            if (d <= 32) {
                int key = (beg + lane < end) ? g_elist[beg + lane] : 0x7fffffff;
#pragma unroll
                for (int ph = 0; ph < 32; ph++) {
                    int odd = ph & 1;
                    bool lo = (((lane ^ odd) & 1) == 0);
                    int partner = lo ? lane + 1 : lane - 1;
                    int pv = __shfl_sync(FULL, key, partner & 31);
                    if (partner >= 0 && partner < 32)
                        key = lo ? min(key, pv) : max(key, pv);
                }
                if (lane < d) g_elist[beg + lane] = key;
            } else if (lane == 0) {
                for (int i = beg + 1; i < end; i++) {
                    int key = g_elist[i];
                    int j = i - 1;
                    while (j >= beg && g_elist[j] > key) { g_elist[j + 1] = g_elist[j]; j--; }
                    g_elist[j + 1] = key;
                }
            }
            __syncwarp();
        }
    }

    const float4* z4 = reinterpret_cast<const float4*>(g_z);
    float4 zd0 = z4[(size_t)n * 16 + cl * 2];
    float4 zd1 = z4[(size_t)n * 16 + cl * 2 + 1];
    float4 at0 = reinterpret_cast<const float4*>(att_l)[cl * 2];
    float4 at1 = reinterpret_cast<const float4*>(att_l)[cl * 2 + 1];

    float m = -1e30f, den = 0.f;
    float4 acc0 = {0, 0, 0, 0}, acc1 = {0, 0, 0, 0};

    for (int cs = beg; cs < end; cs += 32) {
        int p32 = cs + lane;
        int s = n;
        if (p32 < end) {
            int e = g_elist[p32];
            s = (e < EE) ? src[e] : (e - EE);
        }
        int nchunk = min(8, (end - cs + 3) >> 2);
        int sv = __shfl_sync(FULL, s, g);
        float4 zs0 = z4[(size_t)sv * 16 + cl * 2];
        float4 zs1 = z4[(size_t)sv * 16 + cl * 2 + 1];
        for (int it = 0; it < nchunk; it++) {
            int pidx = cs + it * 4 + g;
            bool valid = pidx < end;
            float4 nz0 = zs0, nz1 = zs1;
            if (it + 1 < nchunk) {
                int sv2 = __shfl_sync(FULL, s, (it + 1) * 4 + g);
                nz0 = z4[(size_t)sv2 * 16 + cl * 2];
                nz1 = z4[(size_t)sv2 * 16 + cl * 2 + 1];
            }
            float part =
                lrelu(zs0.x + zd0.x, 0.2f) * at0.x + lrelu(zs0.y + zd0.y, 0.2f) * at0.y +
                lrelu(zs0.z + zd0.z, 0.2f) * at0.z + lrelu(zs0.w + zd0.w, 0.2f) * at0.w +
                lrelu(zs1.x + zd1.x, 0.2f) * at1.x + lrelu(zs1.y + zd1.y, 0.2f) * at1.y +
                lrelu(zs1.z + zd1.z, 0.2f) * at1.z + lrelu(zs1.w + zd1.w, 0.2f) * at1.w;
            part += __shfl_xor_sync(FULL, part, 4);
            part += __shfl_xor_sync(FULL, part, 2);
            part += __shfl_xor_sync(FULL, part, 1);
            float score = valid ? part : -1e30f;
            if (valid && cl == 0) g_score[pidx] = score;
            float nm = fmaxf(m, score);
            float sc = __expf(m - nm);
            float w = __expf(score - nm);
            den = den * sc + w;
            acc0.x = acc0.x * sc + w * zs0.x; acc0.y = acc0.y * sc + w * zs0.y;
            acc0.z = acc0.z * sc + w * zs0.z; acc0.w = acc0.w * sc + w * zs0.w;
            acc1.x = acc1.x * sc + w * zs1.x; acc1.y = acc1.y * sc + w * zs1.y;
            acc1.z = acc1.z * sc + w * zs1.z; acc1.w = acc1.w * sc + w * zs1.w;
            m = nm;
            zs0 = nz0; zs1 = nz1;
        }
    }

    float M = fmaxf(m, __shfl_xor_sync(FULL, m, 8));
    M = fmaxf(M, __shfl_xor_sync(FULL, M, 16));
    float f = __expf(m - M);
    den *= f;
    acc0.x *= f; acc0.y *= f; acc0.z *= f; acc0.w *= f;
    acc1.x *= f; acc1.y *= f; acc1.z *= f; acc1.w *= f;
    den += __shfl_xor_sync(FULL, den, 8);
    den += __shfl_xor_sync(FULL, den, 16);
#pragma unroll
    for (int off = 8; off <= 16; off <<= 1) {
        acc0.x += __shfl_xor_sync(FULL, acc0.x, off);
        acc0.y += __shfl_xor_sync(FULL, acc0.y, off);
        acc0.z += __shfl_xor_sync(FULL, acc0.z, off);
        acc0.w += __shfl_xor_sync(FULL, acc0.w, off);
        acc1.x += __shfl_xor_sync(FULL, acc1.x, off);
        acc1.y += __shfl_xor_sync(FULL, acc1.y, off);
        acc1.z += __shfl_xor_sync(FULL, acc1.z, off);
        acc1.w += __shfl_xor_sync(FULL, acc1.w, off);
    }
    float invd = 1.f / (den + 1e-16f);
    if (g == 0) {
        float4 cb0 = reinterpret_cast<const float4*>(cb_l)[cl * 2];
        float4 cb1 = reinterpret_cast<const float4*>(cb_l)[cl * 2 + 1];
        float4 o0, o1;
        o0.x = acc0.x * invd + cb0.x; o0.y = acc0.y * invd + cb0.y;
        o0.z = acc0.z * invd + cb0.z; o0.w = acc0.w * invd + cb0.w;
        o1.x = acc1.x * invd + cb1.x; o1.y = acc1.y * invd + cb1.y;
        o1.z = acc1.z * invd + cb1.z; o1.w = acc1.w * invd + cb1.w;
        float4* hr = reinterpret_cast<float4*>(g_hraw);
        hr[(size_t)n * 16 + cl * 2] = o0;
        hr[(size_t)n * 16 + cl * 2 + 1] = o1;
    }
    __syncwarp();
    for (int p = beg + lane; p < end; p += 32) {
        alpha_out[g_elist[p]] = __expf(g_score[p] - M) * invd;
    }
}

// ---------------- GEMM MODE2 standalone --------------------------------------
__global__ void __launch_bounds__(GBT, 4) k_gemm2(int layer,
                       const float* __restrict__ bext,
                       const float* __restrict__ gn_w_l,
                       const float* __restrict__ gn_b_l,
                       const float* __restrict__ gn_ms_l) {
    gemm_body<CC, 2>(blockIdx.x, nullptr, layer, bext, gn_w_l, gn_b_l, gn_ms_l);
}

// ---------------- fused GraphNorm stats (RBLK=256) ---------------------------
__global__ void k_redF() {
    int t = threadIdx.x;
    int gid = blockIdx.x * blockDim.x + t;
    const int stride = RBLK * 256;
    float a1[4] = {0, 0, 0, 0}, a2[4] = {0, 0, 0, 0};
    const float4* hr = (const float4*)g_hraw;
    for (int i = gid; i < NN * CC / 4; i += stride) {
        float4 v = hr[i];
        a1[0] += v.x; a2[0] += v.x * v.x;
        a1[1] += v.y; a2[1] += v.y * v.y;
        a1[2] += v.z; a2[2] += v.z * v.z;
        a1[3] += v.w; a2[3] += v.w * v.w;
    }
    __shared__ float sh[256 * 8];
#pragma unroll
    for (int q = 0; q < 4; q++) { sh[t * 8 + q] = a1[q]; sh[t * 8 + 4 + q] = a2[q]; }
    __syncthreads();
    if (t < 16) {
        int c0 = (4 * gid) & 63;
        float r1[4] = {0, 0, 0, 0}, r2[4] = {0, 0, 0, 0};
        for (int j = t; j < 256; j += 16) {
#pragma unroll
            for (int q = 0; q < 4; q++) {
                r1[q] += sh[j * 8 + q];
                r2[q] += sh[j * 8 + 4 + q];
            }
        }
#pragma unroll
        for (int q = 0; q < 4; q++) {
            g_part[blockIdx.x * 128 + c0 + q] = r1[q];
            g_part[blockIdx.x * 128 + 64 + c0 + q] = r2[q];
        }
    }
    __threadfence();
    __shared__ int s_last;
    __shared__ float s_half[2][128];
    if (t == 0) s_last = (atomicAdd(&g_rc, 1) == RBLK - 1) ? 1 : 0;
    __syncthreads();
    if (s_last) {
        int ch = t & 127;
        int b0 = (t < 128) ? 0 : RBLK / 2;
        float s0 = 0.f, s1 = 0.f, s2 = 0.f, s3 = 0.f;
        for (int b = b0; b < b0 + RBLK / 2; b += 4) {
            s0 += g_part[(b + 0) * 128 + ch];
            s1 += g_part[(b + 1) * 128 + ch];
            s2 += g_part[(b + 2) * 128 + ch];
            s3 += g_part[(b + 3) * 128 + ch];
        }
        s_half[t >> 7][ch] = (s0 + s1) + (s2 + s3);
        __syncthreads();
        if (t < 128) g_stat[t] = s_half[0][t] + s_half[1][t];
        __syncthreads();
        if (t == 0) g_rc = 0;
    }
}

__global__ void k_norm_last(const float* __restrict__ gn_w_l,
                            const float* __restrict__ gn_b_l,
                            const float* __restrict__ gn_ms_l,
                            float* __restrict__ out) {
    __shared__ float s_sub[CC], s_w[CC], s_b[CC];
    int t = threadIdx.x;
    if (t < CC) {
        double mu = (double)g_stat[t] / (double)NN;
        double g = (double)gn_ms_l[t];
        double var = (double)g_stat[64 + t] / (double)NN - (2.0 * g - g * g) * mu * mu;
        float rstd = (float)(1.0 / sqrt(var + 1e-5));
        s_sub[t] = (float)(g * mu);
        s_w[t] = gn_w_l[t] * rstd;
        s_b[t] = gn_b_l[t];
    }
    __syncthreads();
    int gid = blockIdx.x * blockDim.x + t;
    const int stride = NORMB * 256;
    const float4* hr = (const float4*)g_hraw;
    float4* o0 = (float4*)out;
    float4* o1 = (float4*)(out + NN * CC);
    for (int i = gid; i < NN * CC / 4; i += stride) {
        int c = (4 * i) & 63;
        float4 v = hr[i];
        v.x = lrelu((v.x - s_sub[c + 0]) * s_w[c + 0] + s_b[c + 0], 0.01f);
        v.y = lrelu((v.y - s_sub[c + 1]) * s_w[c + 1] + s_b[c + 1], 0.01f);
        v.z = lrelu((v.z - s_sub[c + 2]) * s_w[c + 2] + s_b[c + 2], 0.01f);
        v.w = lrelu((v.w - s_sub[c + 3]) * s_w[c + 3] + s_b[c + 3], 0.01f);
        o0[i] = v;
        o1[i] = v;
    }
}

extern "C" void kernel_launch(void* const* d_in, const int* in_sizes, int n_in,
                              void* d_out, int out_size) {
    (void)in_sizes; (void)n_in; (void)out_size;
    const float* x       = (const float*)d_in[0];
    const int*   src     = (const int*)d_in[1];
    const int*   dst     = (const int*)d_in[2];
    const float* bn_w    = (const float*)d_in[3];
    const float* bn_b    = (const float*)d_in[4];
    const float* bn_mean = (const float*)d_in[5];
    const float* bn_var  = (const float*)d_in[6];
    const float* in_W    = (const float*)d_in[7];
    const float* in_b    = (const float*)d_in[8];
    const float* lin_W   = (const float*)d_in[9];
    const float* lin_b   = (const float*)d_in[10];
    const float* att     = (const float*)d_in[11];
    const float* conv_b  = (const float*)d_in[12];
    const float* gn_w    = (const float*)d_in[13];
    const float* gn_b    = (const float*)d_in[14];
    const float* gn_ms   = (const float*)d_in[15];
    float* out = (float*)d_out;

    static bool attr_done = false;
    if (!attr_done) {
        cudaFuncSetAttribute(k_fat1, cudaFuncAttributeMaxDynamicSharedMemorySize, GEMM_SMEM);
        cudaFuncSetAttribute(k_fat2, cudaFuncAttributeMaxDynamicSharedMemorySize, GEMM_SMEM);
        cudaFuncSetAttribute(k_gemm2, cudaFuncAttributeMaxDynamicSharedMemorySize, GEMM_SMEM);
        attr_done = true;
    }

    const int SETUP_B = 4 + (NN + 127) / 128;
    const int HIST_B = (EP + GBT - 1) / GBT;

    k_setup<<<SETUP_B, 128>>>(bn_w, bn_b, bn_mean, bn_var, in_W, in_b, lin_W);  // 0
    k_fat1<<<GB + HIST_B, GBT, GEMM_SMEM>>>(x, dst);                            // 1
    k_fat2<<<GB + NB1, GBT, GEMM_SMEM>>>(lin_b);                                // 2
    k_scan3<<<NB1, 128>>>();                                                    // 3
    k_scatter<<<(EP + 127) / 128, 128>>>(dst);                                  // 4

    for (int l = 0; l < LL; l++) {
        if (l > 0) {
            k_gemm2<<<GB, GBT, GEMM_SMEM>>>(l, lin_b + l * CC,
                                            gn_w + (l - 1) * CC, gn_b + (l - 1) * CC,
                                            gn_ms + (l - 1) * CC);
        }
        if (l == 0)
            k_edge<true><<<(NN * 32 + 255) / 256, 256>>>(src, att, conv_b,
                                                         out + 2 * NN * CC);
        else
            k_edge<false><<<(NN * 32 + 255) / 256, 256>>>(src, att + l * CC, conv_b + l * CC,
                                                          out + 2 * NN * CC + l * EP);
        k_redF<<<RBLK, 256>>>();
    }
    k_norm_last<<<NORMB, 256>>>(gn_w + 3 * CC, gn_b + 3 * CC, gn_ms + 3 * CC, out);
}

// round 17
// speedup vs baseline: 1.0677x; 1.0252x over previous
#include <cuda_runtime.h>
#include <math.h>

#define NN 100000
#define EE 1000000
#define EP (EE + NN)
#define FF 128
#define CC 64
#define LL 4
#define NB1 98
#define RBLK 256
#define GBT 128
#define NT 128
#define SXS 68
#define GEMM_SMEM ((NT * SXS + 64 * 64) * 4)
#define GB ((NN + NT - 1) / NT)
#define NORMB 1184
#define EBT 128

__device__ float  g_h[NN * CC];
__device__ float  g_z[NN * CC];
__device__ float  g_hraw[NN * CC];
__device__ float  g_score[EP];
__device__ int    g_cnt[NN];
__device__ int    g_offs[NN + 1];
__device__ int    g_cur[NN];
__device__ int    g_elist[EP];
__device__ int    g_bsum[NB1 + 2];
__device__ float  g_part[RBLK * 128];
__device__ float  g_stat[128];
__device__ float  g_WTin[FF * CC];
__device__ float  g_WT[LL * CC * CC];
__device__ float  g_bp[CC];
__device__ int    g_rc = 0;

__device__ __forceinline__ float lrelu(float v, float s) { return v >= 0.f ? v : s * v; }

__device__ __forceinline__ void ffma2(unsigned long long &d, unsigned long long a,
                                      unsigned long long b) {
    asm("fma.rn.f32x2 %0, %1, %2, %0;" : "+l"(d) : "l"(a), "l"(b));
}
__device__ __forceinline__ unsigned long long pack2(float x) {
    unsigned long long r;
    unsigned int xi = __float_as_uint(x);
    asm("mov.b64 %0, {%1, %1};" : "=l"(r) : "r"(xi));
    return r;
}
__device__ __forceinline__ void unpack2(unsigned long long v, float &lo, float &hi) {
    unsigned int a, b;
    asm("mov.b64 {%0, %1}, %2;" : "=r"(a), "=r"(b) : "l"(v));
    lo = __uint_as_float(a); hi = __uint_as_float(b);
}

// ---------------- setup (weights + zero g_cnt) --------------------------------
__global__ void k_setup(const float* __restrict__ bn_w, const float* __restrict__ bn_b,
                        const float* __restrict__ bn_mean, const float* __restrict__ bn_var,
                        const float* __restrict__ in_W, const float* __restrict__ in_b,
                        const float* __restrict__ lin_W) {
    int b = blockIdx.x;
    int t = threadIdx.x;
    if (b >= 4) {
        int idx = (b - 4) * 128 + t;
        if (idx < NN) g_cnt[idx] = 0;
        return;
    }
    __shared__ float ss[FF], st[FF];
    if (t < FF) {
        float sv = bn_w[t] * rsqrtf(bn_var[t] + 1e-5f);
        ss[t] = sv;
        st[t] = bn_b[t] - bn_mean[t] * sv;
    }
    __syncthreads();
    for (int idx = t; idx < 32 * CC; idx += blockDim.x) {
        int k = b * 32 + idx / CC, c = idx % CC;
        g_WTin[k * CC + c] = in_W[c * FF + k] * ss[k];
    }
    for (int idx = t; idx < CC * CC; idx += blockDim.x) {
        int k = idx / CC, c = idx % CC;
        g_WT[(b * CC + k) * CC + c] = lin_W[(b * CC + c) * CC + k];
    }
    if (b == 0 && t < CC) {
        float acc = in_b[t];
        for (int k = 0; k < FF; k++) acc += in_W[t * FF + k] * st[k];
        g_bp[t] = acc;
    }
}

// ---------------- GEMM body (R12-proven: 128 thr, x-prefetch schedule) -------
template <int K, int MODE>
__device__ __forceinline__ void gemm_body(int bid,
                       const float* __restrict__ ext_in,
                       int layer,
                       const float* __restrict__ bext,
                       const float* __restrict__ gn_w_l,
                       const float* __restrict__ gn_b_l,
                       const float* __restrict__ gn_ms_l) {
    extern __shared__ float smem[];
    float* sX = smem;
    float* sW = smem + NT * SXS;
    __shared__ float sb[CC], s_sub[CC], s_scl[CC], s_off[CC];
    int t = threadIdx.x;
    if (t < CC) sb[t] = (MODE == 0) ? g_bp[t] : bext[t];
    if (MODE == 2 && t < CC) {
        double mu = (double)g_stat[t] / (double)NN;
        double g = (double)gn_ms_l[t];
        double var = (double)g_stat[64 + t] / (double)NN - (2.0 * g - g * g) * mu * mu;
        float rstd = (float)(1.0 / sqrt(var + 1e-5));
        s_sub[t] = (float)(g * mu);
        s_scl[t] = gn_w_l[t] * rstd;
        s_off[t] = gn_b_l[t];
    }
    __syncthreads();

    const float* xin = (MODE == 0) ? ext_in : (MODE == 1 ? (const float*)g_h
                                                         : (const float*)g_hraw);
    const float* WT = (MODE == 0) ? (const float*)g_WTin
                                  : (const float*)(g_WT + layer * CC * CC);
    int base = bid * NT;
    int tx = t & 7, ty = t >> 3;

    unsigned long long acc[8][4];
#pragma unroll
    for (int i = 0; i < 8; i++)
#pragma unroll
        for (int j = 0; j < 4; j++) acc[i][j] = 0ull;

    const int NCHUNK = K / 64;
    for (int kc = 0; kc < NCHUNK; kc++) {
#pragma unroll
        for (int j = 0; j < 16; j++) {
            int idx = t + j * GBT;
            int node = idx >> 4, kq = idx & 15;
            int gn = base + node;
            float4 v = make_float4(0.f, 0.f, 0.f, 0.f);
            if (gn < NN)
                v = *(const float4*)(xin + (size_t)gn * K + kc * 64 + kq * 4);
            if (MODE == 2) {
                int c = kq * 4;
                v.x = lrelu((v.x - s_sub[c + 0]) * s_scl[c + 0] + s_off[c + 0], 0.01f);
                v.y = lrelu((v.y - s_sub[c + 1]) * s_scl[c + 1] + s_off[c + 1], 0.01f);
                v.z = lrelu((v.z - s_sub[c + 2]) * s_scl[c + 2] + s_off[c + 2], 0.01f);
                v.w = lrelu((v.w - s_sub[c + 3]) * s_scl[c + 3] + s_off[c + 3], 0.01f);
            }
            *(float4*)&sX[node * SXS + kq * 4] = v;
        }
#pragma unroll
        for (int j = 0; j < 8; j++) {
            int idx = t + j * GBT;
            ((float4*)sW)[idx] = ((const float4*)(WT + kc * 64 * CC))[idx];
        }
        __syncthreads();

        float2 xv[8];
#pragma unroll
        for (int i = 0; i < 8; i++)
            xv[i] = *(const float2*)&sX[(ty + i * 16) * SXS + 0];

        for (int kq = 0; kq < 64; kq += 2) {
            ulonglong2 wa0 = *(const ulonglong2*)&sW[kq * 64 + tx * 8];
            ulonglong2 wb0 = *(const ulonglong2*)&sW[kq * 64 + tx * 8 + 4];
            ulonglong2 wa1 = *(const ulonglong2*)&sW[(kq + 1) * 64 + tx * 8];
            ulonglong2 wb1 = *(const ulonglong2*)&sW[(kq + 1) * 64 + tx * 8 + 4];
            float2 xn[8];
            if (kq + 2 < 64) {
#pragma unroll
                for (int i = 0; i < 8; i++)
                    xn[i] = *(const float2*)&sX[(ty + i * 16) * SXS + kq + 2];
            }
#pragma unroll
            for (int i = 0; i < 8; i++) {
                unsigned long long xp = pack2(xv[i].x);
                ffma2(acc[i][0], xp, wa0.x);
                ffma2(acc[i][1], xp, wa0.y);
                ffma2(acc[i][2], xp, wb0.x);
                ffma2(acc[i][3], xp, wb0.y);
            }
#pragma unroll
            for (int i = 0; i < 8; i++) {
                unsigned long long xp = pack2(xv[i].y);
                ffma2(acc[i][0], xp, wa1.x);
                ffma2(acc[i][1], xp, wa1.y);
                ffma2(acc[i][2], xp, wb1.x);
                ffma2(acc[i][3], xp, wb1.y);
            }
            if (kq + 2 < 64) {
#pragma unroll
                for (int i = 0; i < 8; i++) xv[i] = xn[i];
            }
        }
        if (kc + 1 < NCHUNK) __syncthreads();
    }

    float4 b0 = *(const float4*)&sb[tx * 8];
    float4 b1 = *(const float4*)&sb[tx * 8 + 4];
    float* outp = (MODE == 0) ? g_h : g_z;
#pragma unroll
    for (int i = 0; i < 8; i++) {
        int node = base + ty + i * 16;
        if (node >= NN) continue;
        float4 r0, r1;
        unpack2(acc[i][0], r0.x, r0.y);
        unpack2(acc[i][1], r0.z, r0.w);
        unpack2(acc[i][2], r1.x, r1.y);
        unpack2(acc[i][3], r1.z, r1.w);
        r0.x += b0.x; r0.y += b0.y; r0.z += b0.z; r0.w += b0.w;
        r1.x += b1.x; r1.y += b1.y; r1.z += b1.z; r1.w += b1.w;
        if (MODE == 0) {
            r0.x = lrelu(r0.x, 0.01f); r0.y = lrelu(r0.y, 0.01f);
            r0.z = lrelu(r0.z, 0.01f); r0.w = lrelu(r0.w, 0.01f);
            r1.x = lrelu(r1.x, 0.01f); r1.y = lrelu(r1.y, 0.01f);
            r1.z = lrelu(r1.z, 0.01f); r1.w = lrelu(r1.w, 0.01f);
        }
        float* op = outp + (size_t)node * CC + tx * 8;
        *(float4*)op = r0;
        *(float4*)(op + 4) = r1;
    }
}

// ---------------- fat kernels ------------------------------------------------
__global__ void __launch_bounds__(GBT, 4) k_fat1(const float* __restrict__ x,
                                                 const int* __restrict__ dst) {
    if (blockIdx.x < GB) {
        gemm_body<FF, 0>(blockIdx.x, x, 0, nullptr, nullptr, nullptr, nullptr);
    } else {
        int i = (blockIdx.x - GB) * GBT + threadIdx.x;
        if (i < EP) {
            int d = i < EE ? dst[i] : i - EE;
            atomicAdd(&g_cnt[d], 1);
        }
    }
}

__global__ void __launch_bounds__(GBT, 4) k_fat2(const float* __restrict__ lin_b) {
    if (blockIdx.x < GB) {
        gemm_body<CC, 1>(blockIdx.x, nullptr, 0, lin_b, nullptr, nullptr, nullptr);
        return;
    }
    int b = blockIdx.x - GB;
    int t = threadIdx.x;
    int base = b * 1024;
    int loc[8];
    int run = 0;
#pragma unroll
    for (int j = 0; j < 8; j++) {
        int i = base + t * 8 + j;
        int v = (i < NN) ? g_cnt[i] : 0;
        run += v;
        loc[j] = run;
    }
    __shared__ int sT[128];
    sT[t] = run;
    __syncthreads();
    for (int off = 1; off < 128; off <<= 1) {
        int add = (t >= off) ? sT[t - off] : 0;
        __syncthreads();
        sT[t] += add;
        __syncthreads();
    }
    int excl = sT[t] - run;
#pragma unroll
    for (int j = 0; j < 8; j++) {
        int i = base + t * 8 + j;
        if (i < NN) g_cur[i] = excl + loc[j];
    }
    if (t == 127) g_bsum[b] = sT[127];
}

__global__ void k_scan3() {
    __shared__ int sv[128];
    __shared__ int sOff;
    int t = threadIdx.x;
    int b = blockIdx.x;
    sv[t] = (t < b) ? g_bsum[t] : 0;
    __syncthreads();
    for (int off = 64; off >= 1; off >>= 1) {
        if (t < off) sv[t] += sv[t + off];
        __syncthreads();
    }
    if (t == 0) sOff = sv[0];
    __syncthreads();
    int boff = sOff;
    int base = b * 1024;
#pragma unroll
    for (int j = 0; j < 8; j++) {
        int i = base + t * 8 + j;
        if (i < NN) {
            int incl = g_cur[i];
            int ex = incl - g_cnt[i] + boff;
            g_offs[i] = ex;
            g_cur[i] = ex;
            if (i == NN - 1) g_offs[NN] = incl + boff;
        }
    }
}

__global__ void k_scatter(const int* __restrict__ dst) {
    int i = blockIdx.x * blockDim.x + threadIdx.x;
    if (i >= EP) return;
    int d = i < EE ? dst[i] : i - EE;
    int pos = atomicAdd(&g_cur[d], 1);
    g_elist[pos] = i;
}

// ---------------- edge pass (fused segment sort on layer 0) ------------------
// 128-thread blocks (4 warps): finer scheduling granularity for degree skew.
template <bool SORT>
__global__ void k_edge(const int* __restrict__ src,
                       const float* __restrict__ att_l,
                       const float* __restrict__ cb_l,
                       float* __restrict__ alpha_out) {
    const unsigned FULL = 0xffffffffu;
    int warp = (blockIdx.x * blockDim.x + threadIdx.x) >> 5;
    int lane = threadIdx.x & 31;
    if (warp >= NN) return;
    int n = warp;
    int g = lane >> 3, cl = lane & 7;

    int beg = g_offs[n], end = g_offs[n + 1];

    if (SORT) {
        int d = end - beg;
        if (d > 1) {
            if (d <= 32) {
                int key = (beg + lane < end) ? g_elist[beg + lane] : 0x7fffffff;
#pragma unroll
                for (int ph = 0; ph < 32; ph++) {
                    int odd = ph & 1;
                    bool lo = (((lane ^ odd) & 1) == 0);
                    int partner = lo ? lane + 1 : lane - 1;
                    int pv = __shfl_sync(FULL, key, partner & 31);
                    if (partner >= 0 && partner < 32)
                        key = lo ? min(key, pv) : max(key, pv);
                }
                if (lane < d) g_elist[beg + lane] = key;
            } else if (lane == 0) {
                for (int i = beg + 1; i < end; i++) {
                    int key = g_elist[i];
                    int j = i - 1;
                    while (j >= beg && g_elist[j] > key) { g_elist[j + 1] = g_elist[j]; j--; }
                    g_elist[j + 1] = key;
                }
            }
            __syncwarp();
        }
    }

    const float4* z4 = reinterpret_cast<const float4*>(g_z);
    float4 zd0 = z4[(size_t)n * 16 + cl * 2];
    float4 zd1 = z4[(size_t)n * 16 + cl * 2 + 1];
    float4 at0 = reinterpret_cast<const float4*>(att_l)[cl * 2];
    float4 at1 = reinterpret_cast<const float4*>(att_l)[cl * 2 + 1];

    float m = -1e30f, den = 0.f;
    float4 acc0 = {0, 0, 0, 0}, acc1 = {0, 0, 0, 0};

    for (int cs = beg; cs < end; cs += 32) {
        int p32 = cs + lane;
        int s = n;
        if (p32 < end) {
            int e = g_elist[p32];
            s = (e < EE) ? src[e] : (e - EE);
        }
        int nchunk = min(8, (end - cs + 3) >> 2);
        int sv = __shfl_sync(FULL, s, g);
        float4 zs0 = z4[(size_t)sv * 16 + cl * 2];
        float4 zs1 = z4[(size_t)sv * 16 + cl * 2 + 1];
        for (int it = 0; it < nchunk; it++) {
            int pidx = cs + it * 4 + g;
            bool valid = pidx < end;
            float4 nz0 = zs0, nz1 = zs1;
            if (it + 1 < nchunk) {
                int sv2 = __shfl_sync(FULL, s, (it + 1) * 4 + g);
                nz0 = z4[(size_t)sv2 * 16 + cl * 2];
                nz1 = z4[(size_t)sv2 * 16 + cl * 2 + 1];
            }
            float part =
                lrelu(zs0.x + zd0.x, 0.2f) * at0.x + lrelu(zs0.y + zd0.y, 0.2f) * at0.y +
                lrelu(zs0.z + zd0.z, 0.2f) * at0.z + lrelu(zs0.w + zd0.w, 0.2f) * at0.w +
                lrelu(zs1.x + zd1.x, 0.2f) * at1.x + lrelu(zs1.y + zd1.y, 0.2f) * at1.y +
                lrelu(zs1.z + zd1.z, 0.2f) * at1.z + lrelu(zs1.w + zd1.w, 0.2f) * at1.w;
            part += __shfl_xor_sync(FULL, part, 4);
            part += __shfl_xor_sync(FULL, part, 2);
            part += __shfl_xor_sync(FULL, part, 1);
            float score = valid ? part : -1e30f;
            if (valid && cl == 0) g_score[pidx] = score;
            float nm = fmaxf(m, score);
            float sc = __expf(m - nm);
            float w = __expf(score - nm);
            den = den * sc + w;
            acc0.x = acc0.x * sc + w * zs0.x; acc0.y = acc0.y * sc + w * zs0.y;
            acc0.z = acc0.z * sc + w * zs0.z; acc0.w = acc0.w * sc + w * zs0.w;
            acc1.x = acc1.x * sc + w * zs1.x; acc1.y = acc1.y * sc + w * zs1.y;
            acc1.z = acc1.z * sc + w * zs1.z; acc1.w = acc1.w * sc + w * zs1.w;
            m = nm;
            zs0 = nz0; zs1 = nz1;
        }
    }

    float M = fmaxf(m, __shfl_xor_sync(FULL, m, 8));
    M = fmaxf(M, __shfl_xor_sync(FULL, M, 16));
    float f = __expf(m - M);
    den *= f;
    acc0.x *= f; acc0.y *= f; acc0.z *= f; acc0.w *= f;
    acc1.x *= f; acc1.y *= f; acc1.z *= f; acc1.w *= f;
    den += __shfl_xor_sync(FULL, den, 8);
    den += __shfl_xor_sync(FULL, den, 16);
#pragma unroll
    for (int off = 8; off <= 16; off <<= 1) {
        acc0.x += __shfl_xor_sync(FULL, acc0.x, off);
        acc0.y += __shfl_xor_sync(FULL, acc0.y, off);
        acc0.z += __shfl_xor_sync(FULL, acc0.z, off);
        acc0.w += __shfl_xor_sync(FULL, acc0.w, off);
        acc1.x += __shfl_xor_sync(FULL, acc1.x, off);
        acc1.y += __shfl_xor_sync(FULL, acc1.y, off);
        acc1.z += __shfl_xor_sync(FULL, acc1.z, off);
        acc1.w += __shfl_xor_sync(FULL, acc1.w, off);
    }
    float invd = 1.f / (den + 1e-16f);
    if (g == 0) {
        float4 cb0 = reinterpret_cast<const float4*>(cb_l)[cl * 2];
        float4 cb1 = reinterpret_cast<const float4*>(cb_l)[cl * 2 + 1];
        float4 o0, o1;
        o0.x = acc0.x * invd + cb0.x; o0.y = acc0.y * invd + cb0.y;
        o0.z = acc0.z * invd + cb0.z; o0.w = acc0.w * invd + cb0.w;
        o1.x = acc1.x * invd + cb1.x; o1.y = acc1.y * invd + cb1.y;
        o1.z = acc1.z * invd + cb1.z; o1.w = acc1.w * invd + cb1.w;
        float4* hr = reinterpret_cast<float4*>(g_hraw);
        hr[(size_t)n * 16 + cl * 2] = o0;
        hr[(size_t)n * 16 + cl * 2 + 1] = o1;
    }
    __syncwarp();
    for (int p = beg + lane; p < end; p += 32) {
        alpha_out[g_elist[p]] = __expf(g_score[p] - M) * invd;
    }
}

// ---------------- GEMM MODE2 standalone --------------------------------------
__global__ void __launch_bounds__(GBT, 4) k_gemm2(int layer,
                       const float* __restrict__ bext,
                       const float* __restrict__ gn_w_l,
                       const float* __restrict__ gn_b_l,
                       const float* __restrict__ gn_ms_l) {
    gemm_body<CC, 2>(blockIdx.x, nullptr, layer, bext, gn_w_l, gn_b_l, gn_ms_l);
}

// ---------------- fused GraphNorm stats (RBLK=256) ---------------------------
__global__ void k_redF() {
    int t = threadIdx.x;
    int gid = blockIdx.x * blockDim.x + t;
    const int stride = RBLK * 256;
    float a1[4] = {0, 0, 0, 0}, a2[4] = {0, 0, 0, 0};
    const float4* hr = (const float4*)g_hraw;
    for (int i = gid; i < NN * CC / 4; i += stride) {
        float4 v = hr[i];
        a1[0] += v.x; a2[0] += v.x * v.x;
        a1[1] += v.y; a2[1] += v.y * v.y;
        a1[2] += v.z; a2[2] += v.z * v.z;
        a1[3] += v.w; a2[3] += v.w * v.w;
    }
    __shared__ float sh[256 * 8];
#pragma unroll
    for (int q = 0; q < 4; q++) { sh[t * 8 + q] = a1[q]; sh[t * 8 + 4 + q] = a2[q]; }
    __syncthreads();
    if (t < 16) {
        int c0 = (4 * gid) & 63;
        float r1[4] = {0, 0, 0, 0}, r2[4] = {0, 0, 0, 0};
        for (int j = t; j < 256; j += 16) {
#pragma unroll
            for (int q = 0; q < 4; q++) {
                r1[q] += sh[j * 8 + q];
                r2[q] += sh[j * 8 + 4 + q];
            }
        }
#pragma unroll
        for (int q = 0; q < 4; q++) {
            g_part[blockIdx.x * 128 + c0 + q] = r1[q];
            g_part[blockIdx.x * 128 + 64 + c0 + q] = r2[q];
        }
    }
    __threadfence();
    __shared__ int s_last;
    __shared__ float s_half[2][128];
    if (t == 0) s_last = (atomicAdd(&g_rc, 1) == RBLK - 1) ? 1 : 0;
    __syncthreads();
    if (s_last) {
        int ch = t & 127;
        int b0 = (t < 128) ? 0 : RBLK / 2;
        float s0 = 0.f, s1 = 0.f, s2 = 0.f, s3 = 0.f;
        for (int b = b0; b < b0 + RBLK / 2; b += 4) {
            s0 += g_part[(b + 0) * 128 + ch];
            s1 += g_part[(b + 1) * 128 + ch];
            s2 += g_part[(b + 2) * 128 + ch];
            s3 += g_part[(b + 3) * 128 + ch];
        }
        s_half[t >> 7][ch] = (s0 + s1) + (s2 + s3);
        __syncthreads();
        if (t < 128) g_stat[t] = s_half[0][t] + s_half[1][t];
        __syncthreads();
        if (t == 0) g_rc = 0;
    }
}

__global__ void k_norm_last(const float* __restrict__ gn_w_l,
                            const float* __restrict__ gn_b_l,
                            const float* __restrict__ gn_ms_l,
                            float* __restrict__ out) {
    __shared__ float s_sub[CC], s_w[CC], s_b[CC];
    int t = threadIdx.x;
    if (t < CC) {
        double mu = (double)g_stat[t] / (double)NN;
        double g = (double)gn_ms_l[t];
        double var = (double)g_stat[64 + t] / (double)NN - (2.0 * g - g * g) * mu * mu;
        float rstd = (float)(1.0 / sqrt(var + 1e-5));
        s_sub[t] = (float)(g * mu);
        s_w[t] = gn_w_l[t] * rstd;
        s_b[t] = gn_b_l[t];
    }
    __syncthreads();
    int gid = blockIdx.x * blockDim.x + t;
    const int stride = NORMB * 256;
    const float4* hr = (const float4*)g_hraw;
    float4* o0 = (float4*)out;
    float4* o1 = (float4*)(out + NN * CC);
    for (int i = gid; i < NN * CC / 4; i += stride) {
        int c = (4 * i) & 63;
        float4 v = hr[i];
        v.x = lrelu((v.x - s_sub[c + 0]) * s_w[c + 0] + s_b[c + 0], 0.01f);
        v.y = lrelu((v.y - s_sub[c + 1]) * s_w[c + 1] + s_b[c + 1], 0.01f);
        v.z = lrelu((v.z - s_sub[c + 2]) * s_w[c + 2] + s_b[c + 2], 0.01f);
        v.w = lrelu((v.w - s_sub[c + 3]) * s_w[c + 3] + s_b[c + 3], 0.01f);
        o0[i] = v;
        o1[i] = v;
    }
}

extern "C" void kernel_launch(void* const* d_in, const int* in_sizes, int n_in,
                              void* d_out, int out_size) {
    (void)in_sizes; (void)n_in; (void)out_size;
    const float* x       = (const float*)d_in[0];
    const int*   src     = (const int*)d_in[1];
    const int*   dst     = (const int*)d_in[2];
    const float* bn_w    = (const float*)d_in[3];
    const float* bn_b    = (const float*)d_in[4];
    const float* bn_mean = (const float*)d_in[5];
    const float* bn_var  = (const float*)d_in[6];
    const float* in_W    = (const float*)d_in[7];
    const float* in_b    = (const float*)d_in[8];
    const float* lin_W   = (const float*)d_in[9];
    const float* lin_b   = (const float*)d_in[10];
    const float* att     = (const float*)d_in[11];
    const float* conv_b  = (const float*)d_in[12];
    const float* gn_w    = (const float*)d_in[13];
    const float* gn_b    = (const float*)d_in[14];
    const float* gn_ms   = (const float*)d_in[15];
    float* out = (float*)d_out;

    static bool attr_done = false;
    if (!attr_done) {
        cudaFuncSetAttribute(k_fat1, cudaFuncAttributeMaxDynamicSharedMemorySize, GEMM_SMEM);
        cudaFuncSetAttribute(k_fat2, cudaFuncAttributeMaxDynamicSharedMemorySize, GEMM_SMEM);
        cudaFuncSetAttribute(k_gemm2, cudaFuncAttributeMaxDynamicSharedMemorySize, GEMM_SMEM);
        attr_done = true;
    }

    const int SETUP_B = 4 + (NN + 127) / 128;
    const int HIST_B = (EP + GBT - 1) / GBT;

    k_setup<<<SETUP_B, 128>>>(bn_w, bn_b, bn_mean, bn_var, in_W, in_b, lin_W);  // 0
    k_fat1<<<GB + HIST_B, GBT, GEMM_SMEM>>>(x, dst);                            // 1
    k_fat2<<<GB + NB1, GBT, GEMM_SMEM>>>(lin_b);                                // 2
    k_scan3<<<NB1, 128>>>();                                                    // 3
    k_scatter<<<(EP + 127) / 128, 128>>>(dst);                                  // 4

    for (int l = 0; l < LL; l++) {
        if (l > 0) {
            k_gemm2<<<GB, GBT, GEMM_SMEM>>>(l, lin_b + l * CC,
                                            gn_w + (l - 1) * CC, gn_b + (l - 1) * CC,
                                            gn_ms + (l - 1) * CC);
        }
        if (l == 0)
            k_edge<true><<<(NN * 32 + EBT - 1) / EBT, EBT>>>(src, att, conv_b,
                                                             out + 2 * NN * CC);
        else
            k_edge<false><<<(NN * 32 + EBT - 1) / EBT, EBT>>>(src, att + l * CC,
                                                              conv_b + l * CC,
                                                              out + 2 * NN * CC + l * EP);
        k_redF<<<RBLK, 256>>>();
    }
    k_norm_last<<<NORMB, 256>>>(gn_w + 3 * CC, gn_b + 3 * CC, gn_ms + 3 * CC, out);
}